// round 4
// baseline (speedup 1.0000x reference)
#include <cuda_runtime.h>
#include <math.h>

#define B_  4
#define L_  2048
#define D_  1024
#define H_  16
#define DH  64
#define ML  ((size_t)B_ * L_)          // 8192 rows

// ---------------- scratch (no allocation allowed) ----------------
__device__ float g_qkv[ML * 3 * D_];   // 8192 x 3072
__device__ float g_q[ML * D_];         // [B,H,L,Dh]
__device__ float g_k[ML * D_];
__device__ float g_v[ML * D_];
__device__ float g_att[ML * D_];       // [B,L,D]
__device__ float g_cos[L_ * 32];
__device__ float g_sin[L_ * 32];

// ---------------- RoPE table (double-accurate, matches numpy f32 path) ---
__global__ void rope_table_kernel() {
    int idx = blockIdx.x * blockDim.x + threadIdx.x;   // L_*32 = 65536
    int i = idx & 31;
    int l = idx >> 5;
    // inv_freq = 10000^(-i/32), rounded to f32 like numpy
    double invd = exp(-(double)i * (9.210340371976184 / 32.0));
    float invf = (float)invd;
    float freq = (float)l * invf;                      // f32 product like numpy einsum
    g_cos[idx] = (float)cos((double)freq);
    g_sin[idx] = (float)sin((double)freq);
}

// ---------------- fp32 SGEMM: C = A(MxK) * B(KxN) + bias ----------------
// BM=BN=128, BK=8, 256 threads, 8x8 microtile. All dims divide evenly.
__global__ __launch_bounds__(256) void sgemm_bias_kernel(
    const float* __restrict__ A, const float* __restrict__ Bm,
    const float* __restrict__ bias, float* __restrict__ C,
    int M, int N, int K)
{
    __shared__ float As[8][128];
    __shared__ float Bs[8][128];

    int tid = threadIdx.x;
    int bm = blockIdx.y * 128;
    int bn = blockIdx.x * 128;

    int arow = tid >> 1;            // 0..127
    int acol = (tid & 1) * 4;       // 0 or 4
    int brow = tid >> 5;            // 0..7
    int bcol = (tid & 31) * 4;      // 0..124

    int tx = tid & 15, ty = tid >> 4;

    float acc[8][8];
    #pragma unroll
    for (int i = 0; i < 8; i++)
        #pragma unroll
        for (int j = 0; j < 8; j++) acc[i][j] = 0.f;

    const float* Ap = A + (size_t)bm * K;
    const float* Bp = Bm + bn;

    for (int k0 = 0; k0 < K; k0 += 8) {
        float4 av = *reinterpret_cast<const float4*>(Ap + (size_t)arow * K + k0 + acol);
        As[acol + 0][arow] = av.x;
        As[acol + 1][arow] = av.y;
        As[acol + 2][arow] = av.z;
        As[acol + 3][arow] = av.w;
        float4 bv = *reinterpret_cast<const float4*>(Bp + (size_t)(k0 + brow) * N + bcol);
        *reinterpret_cast<float4*>(&Bs[brow][bcol]) = bv;
        __syncthreads();

        #pragma unroll
        for (int k = 0; k < 8; k++) {
            float ar[8], br[8];
            float4 a0 = *reinterpret_cast<const float4*>(&As[k][ty * 8]);
            float4 a1 = *reinterpret_cast<const float4*>(&As[k][ty * 8 + 4]);
            float4 b0 = *reinterpret_cast<const float4*>(&Bs[k][tx * 8]);
            float4 b1 = *reinterpret_cast<const float4*>(&Bs[k][tx * 8 + 4]);
            ar[0]=a0.x; ar[1]=a0.y; ar[2]=a0.z; ar[3]=a0.w;
            ar[4]=a1.x; ar[5]=a1.y; ar[6]=a1.z; ar[7]=a1.w;
            br[0]=b0.x; br[1]=b0.y; br[2]=b0.z; br[3]=b0.w;
            br[4]=b1.x; br[5]=b1.y; br[6]=b1.z; br[7]=b1.w;
            #pragma unroll
            for (int i = 0; i < 8; i++)
                #pragma unroll
                for (int j = 0; j < 8; j++)
                    acc[i][j] = fmaf(ar[i], br[j], acc[i][j]);
        }
        __syncthreads();
    }

    #pragma unroll
    for (int i = 0; i < 8; i++) {
        size_t row = bm + ty * 8 + i;
        #pragma unroll
        for (int j = 0; j < 8; j += 4) {
            int col = bn + tx * 8 + j;
            float4 o;
            o.x = acc[i][j + 0] + bias[col + 0];
            o.y = acc[i][j + 1] + bias[col + 1];
            o.z = acc[i][j + 2] + bias[col + 2];
            o.w = acc[i][j + 3] + bias[col + 3];
            *reinterpret_cast<float4*>(C + row * N + col) = o;
        }
    }
}

// ---------------- split qkv + RoPE, write [B,H,L,Dh] --------------------
__global__ void rope_split_kernel(const float* __restrict__ qkv,
    float* __restrict__ Q, float* __restrict__ K, float* __restrict__ V)
{
    int idx = blockIdx.x * blockDim.x + threadIdx.x;   // B*L*H*32 = 2^22
    int i = idx & 31;
    int h = (idx >> 5) & 15;
    int l = (idx >> 9) & 2047;
    int b = idx >> 20;
    const float* base = qkv + ((size_t)(b * L_ + l)) * (3 * D_) + h * DH;
    float c = g_cos[l * 32 + i];
    float s = g_sin[l * 32 + i];
    float q1 = base[2 * i],        q2 = base[2 * i + 1];
    float k1 = base[D_ + 2 * i],   k2 = base[D_ + 2 * i + 1];
    size_t o = ((size_t)((b * H_ + h) * L_ + l)) * DH + 2 * i;
    Q[o]     = q1 * c - q2 * s;
    Q[o + 1] = q1 * s + q2 * c;
    K[o]     = k1 * c - k2 * s;
    K[o + 1] = k1 * s + k2 * c;
    V[o]     = base[2 * D_ + 2 * i];
    V[o + 1] = base[2 * D_ + 2 * i + 1];
}

// ---------------- causal flash attention, fp32 --------------------------
// grid (32 q-tiles, 64 bh), 256 threads, 64x64 tiles, 4x4 microtile.
#define NEG_BIG (-3.402823466e38f)
__global__ __launch_bounds__(256) void attn_kernel(
    const float* __restrict__ Q, const float* __restrict__ K,
    const float* __restrict__ V, const int* __restrict__ mask,
    float* __restrict__ O)
{
    extern __shared__ float sh[];
    float* Qs  = sh;                 // [64][65]
    float* KPs = sh + 64 * 65;       // K tile, reused as P tile
    float* Vs  = sh + 2 * 64 * 65;   // [64][65]
    int*  kmsk = (int*)(sh + 3 * 64 * 65);

    const int qt = blockIdx.x;
    const int bh = blockIdx.y;
    const int b = bh >> 4, h = bh & 15;
    const float* Qp = Q + ((size_t)bh * L_ + qt * 64) * DH;
    const float* Kp = K + (size_t)bh * L_ * DH;
    const float* Vp = V + (size_t)bh * L_ * DH;
    const int* mp = mask + b * L_;

    int tid = threadIdx.x;
    int tx = tid & 15, ty = tid >> 4;
    int r0 = ty * 4, c0 = tx * 4;

    for (int idx = tid; idx < 64 * 64; idx += 256) {
        int r = idx >> 6, c = idx & 63;
        Qs[r * 65 + c] = Qp[(size_t)r * DH + c] * 0.125f;  // fold 1/sqrt(64)
    }

    float m_[4], l_[4], acc[4][4];
    #pragma unroll
    for (int i = 0; i < 4; i++) {
        m_[i] = NEG_BIG; l_[i] = 0.f;
        #pragma unroll
        for (int j = 0; j < 4; j++) acc[i][j] = 0.f;
    }

    const int kvend = (qt + 1) * 64;
    for (int k0 = 0; k0 < kvend; k0 += 64) {
        __syncthreads();   // previous PV reads of KPs/Vs done
        for (int idx = tid; idx < 64 * 64; idx += 256) {
            int r = idx >> 6, c = idx & 63;
            KPs[r * 65 + c] = Kp[(size_t)(k0 + r) * DH + c];
            Vs[r * 65 + c]  = Vp[(size_t)(k0 + r) * DH + c];
        }
        if (tid < 64) kmsk[tid] = mp[k0 + tid];
        __syncthreads();

        // S = Q K^T  (scale pre-folded into Qs)
        float s[4][4];
        #pragma unroll
        for (int i = 0; i < 4; i++)
            #pragma unroll
            for (int j = 0; j < 4; j++) s[i][j] = 0.f;
        for (int d = 0; d < 64; d++) {
            float qv[4], kv[4];
            #pragma unroll
            for (int i = 0; i < 4; i++) qv[i] = Qs[(r0 + i) * 65 + d];
            #pragma unroll
            for (int j = 0; j < 4; j++) kv[j] = KPs[(c0 + j) * 65 + d];
            #pragma unroll
            for (int i = 0; i < 4; i++)
                #pragma unroll
                for (int j = 0; j < 4; j++)
                    s[i][j] = fmaf(qv[i], kv[j], s[i][j]);
        }

        // mask + online softmax update
        float alpha[4];
        #pragma unroll
        for (int i = 0; i < 4; i++) {
            int qg = qt * 64 + r0 + i;
            float mx = NEG_BIG;
            #pragma unroll
            for (int j = 0; j < 4; j++) {
                int kg = k0 + c0 + j;
                bool keep = (kg <= qg) && (kmsk[c0 + j] != 0);
                if (!keep) s[i][j] = NEG_BIG;
                mx = fmaxf(mx, s[i][j]);
            }
            #pragma unroll
            for (int off = 8; off >= 1; off >>= 1)
                mx = fmaxf(mx, __shfl_xor_sync(0xffffffffu, mx, off, 16));
            float mnew = fmaxf(m_[i], mx);
            alpha[i] = expf(m_[i] - mnew);
            float ls = 0.f;
            #pragma unroll
            for (int j = 0; j < 4; j++) {
                s[i][j] = expf(s[i][j] - mnew);
                ls += s[i][j];
            }
            #pragma unroll
            for (int off = 8; off >= 1; off >>= 1)
                ls += __shfl_xor_sync(0xffffffffu, ls, off, 16);
            l_[i] = l_[i] * alpha[i] + ls;
            m_[i] = mnew;
        }

        __syncthreads();   // all threads done reading KPs as K
        #pragma unroll
        for (int i = 0; i < 4; i++)
            #pragma unroll
            for (int j = 0; j < 4; j++)
                KPs[(r0 + i) * 65 + c0 + j] = s[i][j];
        __syncthreads();   // P tile ready

        // O = O*alpha + P @ V
        #pragma unroll
        for (int i = 0; i < 4; i++)
            #pragma unroll
            for (int j = 0; j < 4; j++)
                acc[i][j] *= alpha[i];
        for (int kk = 0; kk < 64; kk++) {
            float pv[4], vv[4];
            #pragma unroll
            for (int i = 0; i < 4; i++) pv[i] = KPs[(r0 + i) * 65 + kk];
            #pragma unroll
            for (int j = 0; j < 4; j++) vv[j] = Vs[kk * 65 + c0 + j];
            #pragma unroll
            for (int i = 0; i < 4; i++)
                #pragma unroll
                for (int j = 0; j < 4; j++)
                    acc[i][j] = fmaf(pv[i], vv[j], acc[i][j]);
        }
    }

    // epilogue: write [B, L, D] layout for the proj GEMM
    #pragma unroll
    for (int i = 0; i < 4; i++) {
        float invl = 1.0f / l_[i];
        int qg = qt * 64 + r0 + i;
        #pragma unroll
        for (int j = 0; j < 4; j++)
            O[((size_t)(b * L_ + qg)) * D_ + h * DH + c0 + j] = acc[i][j] * invl;
    }
}

// ---------------- launch ------------------------------------------------
extern "C" void kernel_launch(void* const* d_in, const int* in_sizes, int n_in,
                              void* d_out, int out_size) {
    const float* x     = (const float*)d_in[0];
    const float* Wqkv  = (const float*)d_in[1];
    const float* bqkv  = (const float*)d_in[2];
    const float* Wproj = (const float*)d_in[3];
    const float* bproj = (const float*)d_in[4];
    const int*   mask  = (const int*)d_in[5];
    float* out = (float*)d_out;

    float *qkv, *q, *k, *v, *att;
    cudaGetSymbolAddress((void**)&qkv, g_qkv);
    cudaGetSymbolAddress((void**)&q,   g_q);
    cudaGetSymbolAddress((void**)&k,   g_k);
    cudaGetSymbolAddress((void**)&v,   g_v);
    cudaGetSymbolAddress((void**)&att, g_att);

    int attn_smem = (3 * 64 * 65 + 64) * (int)sizeof(float);   // 50176 B
    cudaFuncSetAttribute(attn_kernel,
                         cudaFuncAttributeMaxDynamicSharedMemorySize, attn_smem);

    // 1) RoPE table
    rope_table_kernel<<<(L_ * 32) / 256, 256>>>();

    // 2) QKV GEMM: [8192,1024] x [1024,3072]
    sgemm_bias_kernel<<<dim3(3 * D_ / 128, ML / 128), 256>>>(
        x, Wqkv, bqkv, qkv, (int)ML, 3 * D_, D_);

    // 3) split + RoPE -> [B,H,L,Dh]
    rope_split_kernel<<<(B_ * L_ * H_ * 32) / 256, 256>>>(qkv, q, k, v);

    // 4) causal flash attention -> [B,L,D]
    attn_kernel<<<dim3(L_ / 64, B_ * H_), 256, attn_smem>>>(q, k, v, mask, att);

    // 5) output projection: [8192,1024] x [1024,1024] -> d_out
    sgemm_bias_kernel<<<dim3(D_ / 128, ML / 128), 256>>>(
        att, Wproj, bproj, out, (int)ML, D_, D_);
}

// round 9
// speedup vs baseline: 1.4221x; 1.4221x over previous
#include <cuda_runtime.h>
#include <cuda_bf16.h>
#include <math.h>
#include <stdint.h>

#define B_  4
#define L_  2048
#define D_  1024
#define H_  16
#define DH  64
#define ML  ((size_t)B_ * L_)          // 8192 rows

// ---------------- scratch (no allocation allowed) ----------------
__device__ float g_qkv[ML * 3 * D_];   // 8192 x 3072
__device__ float g_q[ML * D_];         // [B,H,L,Dh]
__device__ float g_k[ML * D_];
__device__ float g_v[ML * D_];
__device__ float g_att[ML * D_];       // [B,L,D]
__device__ float g_cos[L_ * 32];
__device__ float g_sin[L_ * 32];
// bf16 hi/lo operand buffers for tensor-core GEMMs
__device__ __nv_bfloat16 g_ahi[ML * D_];        // A (x, then att) hi
__device__ __nv_bfloat16 g_alo[ML * D_];        // A lo
__device__ __nv_bfloat16 g_wqhi[3 * D_ * D_];   // W_qkv^T hi  [3D, D]
__device__ __nv_bfloat16 g_wqlo[3 * D_ * D_];
__device__ __nv_bfloat16 g_wphi[D_ * D_];       // W_proj^T hi [D, D]
__device__ __nv_bfloat16 g_wplo[D_ * D_];

// ================= helpers =================
__device__ __forceinline__ uint32_t smem_u32(const void* p) {
    uint32_t a;
    asm("{ .reg .u64 t; cvta.to.shared.u64 t, %1; cvt.u32.u64 %0, t; }" : "=r"(a) : "l"(p));
    return a;
}
__device__ __forceinline__ void cp_async16(uint32_t smaddr, const void* gaddr) {
    asm volatile("cp.async.cg.shared.global [%0], [%1], 16;" :: "r"(smaddr), "l"(gaddr));
}
#define CP_COMMIT() asm volatile("cp.async.commit_group;" ::: "memory")
#define CP_WAIT(n)  asm volatile("cp.async.wait_group %0;" :: "n"(n) : "memory")

__device__ __forceinline__ void ldmx4(uint32_t* r, uint32_t addr) {
    asm volatile("ldmatrix.sync.aligned.m8n8.x4.shared.b16 {%0,%1,%2,%3}, [%4];"
        : "=r"(r[0]), "=r"(r[1]), "=r"(r[2]), "=r"(r[3]) : "r"(addr));
}
__device__ __forceinline__ void mma_bf16(float* d, const uint32_t* a, const uint32_t* b) {
    asm volatile("mma.sync.aligned.m16n8k16.row.col.f32.bf16.bf16.f32 "
        "{%0,%1,%2,%3}, {%4,%5,%6,%7}, {%8,%9}, {%0,%1,%2,%3};"
        : "+f"(d[0]), "+f"(d[1]), "+f"(d[2]), "+f"(d[3])
        : "r"(a[0]), "r"(a[1]), "r"(a[2]), "r"(a[3]), "r"(b[0]), "r"(b[1]));
}

// ---------------- RoPE table (double-accurate, matches numpy f32 path) ---
__global__ void rope_table_kernel() {
    int idx = blockIdx.x * blockDim.x + threadIdx.x;   // L_*32 = 65536
    int i = idx & 31;
    int l = idx >> 5;
    double invd = exp(-(double)i * (9.210340371976184 / 32.0));
    float invf = (float)invd;
    float freq = (float)l * invf;
    g_cos[idx] = (float)cos((double)freq);
    g_sin[idx] = (float)sin((double)freq);
}

// ---------------- fp32 -> bf16 hi/lo split (elementwise) ----------------
__global__ void convert_split_kernel(const float* __restrict__ in,
    __nv_bfloat16* __restrict__ hi, __nv_bfloat16* __restrict__ lo)
{
    int i = blockIdx.x * blockDim.x + threadIdx.x;    // n/4 threads
    float4 v = ((const float4*)in)[i];
    __nv_bfloat16 h0 = __float2bfloat16(v.x);
    __nv_bfloat16 h1 = __float2bfloat16(v.y);
    __nv_bfloat16 h2 = __float2bfloat16(v.z);
    __nv_bfloat16 h3 = __float2bfloat16(v.w);
    __nv_bfloat16 l0 = __float2bfloat16(v.x - __bfloat162float(h0));
    __nv_bfloat16 l1 = __float2bfloat16(v.y - __bfloat162float(h1));
    __nv_bfloat16 l2 = __float2bfloat16(v.z - __bfloat162float(h2));
    __nv_bfloat16 l3 = __float2bfloat16(v.w - __bfloat162float(h3));
    __nv_bfloat162 hp0; hp0.x = h0; hp0.y = h1;
    __nv_bfloat162 hp1; hp1.x = h2; hp1.y = h3;
    __nv_bfloat162 lp0; lp0.x = l0; lp0.y = l1;
    __nv_bfloat162 lp1; lp1.x = l2; lp1.y = l3;
    ((__nv_bfloat162*)hi)[2 * i] = hp0;
    ((__nv_bfloat162*)hi)[2 * i + 1] = hp1;
    ((__nv_bfloat162*)lo)[2 * i] = lp0;
    ((__nv_bfloat162*)lo)[2 * i + 1] = lp1;
}

// ---------------- W [K,N] fp32 -> W^T [N,K] bf16 hi/lo ------------------
__global__ void transpose_split_kernel(const float* __restrict__ W,
    __nv_bfloat16* __restrict__ Thi, __nv_bfloat16* __restrict__ Tlo, int Kd, int Nd)
{
    __shared__ float t[32][33];
    int k0 = blockIdx.x * 32, n0 = blockIdx.y * 32;
    int tx = threadIdx.x, ty = threadIdx.y;
    #pragma unroll
    for (int r = ty; r < 32; r += 8)
        t[r][tx] = W[(size_t)(k0 + r) * Nd + n0 + tx];
    __syncthreads();
    #pragma unroll
    for (int r = ty; r < 32; r += 8) {
        float v = t[tx][r];
        __nv_bfloat16 h = __float2bfloat16(v);
        __nv_bfloat16 l = __float2bfloat16(v - __bfloat162float(h));
        size_t o = (size_t)(n0 + r) * Kd + k0 + tx;
        Thi[o] = h;
        Tlo[o] = l;
    }
}

// ---------------- mma.sync bf16 split GEMM ------------------------------
// C[M,N] = (Ahi+Alo)[M,K] * (Bhi+Blo)[N,K]^T + bias (drop lo*lo).
// 128x128 tile, BK=32, 256 threads (8 warps, 2x4), cp.async double buffer.
// smem tile: 128 rows x 32 bf16 (64B data), row stride 80B -> 10240 B/tile.
#define T_STRIDE 80
#define T_BYTES  (128 * T_STRIDE)      // 10240
#define BUF_BYTES (4 * T_BYTES)        // Ahi, Alo, Bhi, Blo = 40960
#define GEMM_SMEM (2 * BUF_BYTES)      // 81920

__global__ __launch_bounds__(256, 1) void gemm_bf16_kernel(
    const __nv_bfloat16* __restrict__ Ahi, const __nv_bfloat16* __restrict__ Alo,
    const __nv_bfloat16* __restrict__ Bhi, const __nv_bfloat16* __restrict__ Blo,
    const float* __restrict__ bias, float* __restrict__ C, int N, int K)
{
    extern __shared__ char smraw[];
    const uint32_t smb = smem_u32(smraw);
    const int tid = threadIdx.x;
    const int wid = tid >> 5, lane = tid & 31;
    const int wr = wid & 1, wc = wid >> 1;         // warp 64-row half, 32-col quarter
    const int bn = blockIdx.x * 128, bm = blockIdx.y * 128;

    const char* gp[4];
    gp[0] = (const char*)(Ahi + (size_t)bm * K);
    gp[1] = (const char*)(Alo + (size_t)bm * K);
    gp[2] = (const char*)(Bhi + (size_t)bn * K);
    gp[3] = (const char*)(Blo + (size_t)bn * K);

    const int NKB = K / 32;

    // per-thread load coords: 2 chunks per tile (512 chunks / 256 thr)
    const int r0l = tid >> 2;            // rows for half 0: tid/4 (0..63)... see idx below
    (void)r0l;

    auto issue_loads = [&](int kb, int buf) {
        uint32_t sbase = smb + buf * BUF_BYTES;
        #pragma unroll
        for (int op = 0; op < 4; op++) {
            #pragma unroll
            for (int half = 0; half < 2; half++) {
                int idx = half * 256 + tid;          // 0..511
                int row = idx >> 2, c = idx & 3;
                const void* g = gp[op] + ((size_t)row * K + kb * 32 + c * 8) * 2;
                uint32_t s = sbase + op * T_BYTES + row * T_STRIDE + c * 16;
                cp_async16(s, g);
            }
        }
    };

    float acc[4][4][4];
    #pragma unroll
    for (int i = 0; i < 4; i++)
        #pragma unroll
        for (int j = 0; j < 4; j++)
            #pragma unroll
            for (int r = 0; r < 4; r++) acc[i][j][r] = 0.f;

    issue_loads(0, 0);
    CP_COMMIT();

    const int lr = lane & 15, lh = lane >> 4;          // A ldmatrix coords
    const int bj = lane >> 4, bch = (lane >> 3) & 1, bn8 = lane & 7;  // B coords

    for (int kb = 0; kb < NKB; kb++) {
        int buf = kb & 1;
        if (kb + 1 < NKB) { issue_loads(kb + 1, buf ^ 1); CP_COMMIT(); CP_WAIT(1); }
        else             { CP_WAIT(0); }
        __syncthreads();

        uint32_t sA_hi = smb + buf * BUF_BYTES;
        uint32_t sA_lo = sA_hi + T_BYTES;
        uint32_t sB_hi = sA_hi + 2 * T_BYTES;
        uint32_t sB_lo = sA_hi + 3 * T_BYTES;

        #pragma unroll
        for (int s = 0; s < 2; s++) {
            uint32_t ahi[4][4], alo[4][4], bhi[4][2], blo[4][2];
            #pragma unroll
            for (int i = 0; i < 4; i++) {
                uint32_t off = (uint32_t)((wr * 64 + i * 16 + lr) * T_STRIDE + (s * 2 + lh) * 16);
                ldmx4(ahi[i], sA_hi + off);
                ldmx4(alo[i], sA_lo + off);
            }
            #pragma unroll
            for (int jp = 0; jp < 2; jp++) {
                uint32_t tmp[4];
                uint32_t off = (uint32_t)((wc * 32 + (2 * jp + bj) * 8 + bn8) * T_STRIDE
                                          + (s * 2 + bch) * 16);
                ldmx4(tmp, sB_hi + off);
                bhi[2 * jp][0] = tmp[0]; bhi[2 * jp][1] = tmp[1];
                bhi[2 * jp + 1][0] = tmp[2]; bhi[2 * jp + 1][1] = tmp[3];
                ldmx4(tmp, sB_lo + off);
                blo[2 * jp][0] = tmp[0]; blo[2 * jp][1] = tmp[1];
                blo[2 * jp + 1][0] = tmp[2]; blo[2 * jp + 1][1] = tmp[3];
            }
            #pragma unroll
            for (int i = 0; i < 4; i++)
                #pragma unroll
                for (int j = 0; j < 4; j++) {
                    mma_bf16(acc[i][j], ahi[i], bhi[j]);
                    mma_bf16(acc[i][j], ahi[i], blo[j]);
                    mma_bf16(acc[i][j], alo[i], bhi[j]);
                }
        }
        __syncthreads();
    }

    // epilogue: d0,d1 -> (row, col..col+1); d2,d3 -> (row+8, ...)
    #pragma unroll
    for (int i = 0; i < 4; i++) {
        int row = bm + wr * 64 + i * 16 + (lane >> 2);
        #pragma unroll
        for (int j = 0; j < 4; j++) {
            int col = bn + wc * 32 + j * 8 + 2 * (lane & 3);
            float b0 = bias[col], b1 = bias[col + 1];
            float2 o0; o0.x = acc[i][j][0] + b0; o0.y = acc[i][j][1] + b1;
            float2 o1; o1.x = acc[i][j][2] + b0; o1.y = acc[i][j][3] + b1;
            *(float2*)(C + (size_t)row * N + col) = o0;
            *(float2*)(C + (size_t)(row + 8) * N + col) = o1;
        }
    }
}

// ---------------- split qkv + RoPE, write [B,H,L,Dh] --------------------
__global__ void rope_split_kernel(const float* __restrict__ qkv,
    float* __restrict__ Q, float* __restrict__ K, float* __restrict__ V)
{
    int idx = blockIdx.x * blockDim.x + threadIdx.x;   // B*L*H*32 = 2^22
    int i = idx & 31;
    int h = (idx >> 5) & 15;
    int l = (idx >> 9) & 2047;
    int b = idx >> 20;
    const float* base = qkv + ((size_t)(b * L_ + l)) * (3 * D_) + h * DH;
    float c = g_cos[l * 32 + i];
    float s = g_sin[l * 32 + i];
    float q1 = base[2 * i],        q2 = base[2 * i + 1];
    float k1 = base[D_ + 2 * i],   k2 = base[D_ + 2 * i + 1];
    size_t o = ((size_t)((b * H_ + h) * L_ + l)) * DH + 2 * i;
    Q[o]     = q1 * c - q2 * s;
    Q[o + 1] = q1 * s + q2 * c;
    K[o]     = k1 * c - k2 * s;
    K[o + 1] = k1 * s + k2 * c;
    V[o]     = base[2 * D_ + 2 * i];
    V[o + 1] = base[2 * D_ + 2 * i + 1];
}

// ---------------- causal flash attention, fp32 (unchanged) --------------
#define NEG_BIG (-3.402823466e38f)
__global__ __launch_bounds__(256) void attn_kernel(
    const float* __restrict__ Q, const float* __restrict__ K,
    const float* __restrict__ V, const int* __restrict__ mask,
    float* __restrict__ O)
{
    extern __shared__ float sh[];
    float* Qs  = sh;                 // [64][65]
    float* KPs = sh + 64 * 65;       // K tile, reused as P tile
    float* Vs  = sh + 2 * 64 * 65;   // [64][65]
    int*  kmsk = (int*)(sh + 3 * 64 * 65);

    const int qt = blockIdx.x;
    const int bh = blockIdx.y;
    const int b = bh >> 4, h = bh & 15;
    const float* Qp = Q + ((size_t)bh * L_ + qt * 64) * DH;
    const float* Kp = K + (size_t)bh * L_ * DH;
    const float* Vp = V + (size_t)bh * L_ * DH;
    const int* mp = mask + b * L_;

    int tid = threadIdx.x;
    int tx = tid & 15, ty = tid >> 4;
    int r0 = ty * 4, c0 = tx * 4;

    for (int idx = tid; idx < 64 * 64; idx += 256) {
        int r = idx >> 6, c = idx & 63;
        Qs[r * 65 + c] = Qp[(size_t)r * DH + c] * 0.125f;
    }

    float m_[4], l_[4], acc[4][4];
    #pragma unroll
    for (int i = 0; i < 4; i++) {
        m_[i] = NEG_BIG; l_[i] = 0.f;
        #pragma unroll
        for (int j = 0; j < 4; j++) acc[i][j] = 0.f;
    }

    const int kvend = (qt + 1) * 64;
    for (int k0 = 0; k0 < kvend; k0 += 64) {
        __syncthreads();
        for (int idx = tid; idx < 64 * 64; idx += 256) {
            int r = idx >> 6, c = idx & 63;
            KPs[r * 65 + c] = Kp[(size_t)(k0 + r) * DH + c];
            Vs[r * 65 + c]  = Vp[(size_t)(k0 + r) * DH + c];
        }
        if (tid < 64) kmsk[tid] = mp[k0 + tid];
        __syncthreads();

        float s[4][4];
        #pragma unroll
        for (int i = 0; i < 4; i++)
            #pragma unroll
            for (int j = 0; j < 4; j++) s[i][j] = 0.f;
        for (int d = 0; d < 64; d++) {
            float qv[4], kv[4];
            #pragma unroll
            for (int i = 0; i < 4; i++) qv[i] = Qs[(r0 + i) * 65 + d];
            #pragma unroll
            for (int j = 0; j < 4; j++) kv[j] = KPs[(c0 + j) * 65 + d];
            #pragma unroll
            for (int i = 0; i < 4; i++)
                #pragma unroll
                for (int j = 0; j < 4; j++)
                    s[i][j] = fmaf(qv[i], kv[j], s[i][j]);
        }

        float alpha[4];
        #pragma unroll
        for (int i = 0; i < 4; i++) {
            int qg = qt * 64 + r0 + i;
            float mx = NEG_BIG;
            #pragma unroll
            for (int j = 0; j < 4; j++) {
                int kg = k0 + c0 + j;
                bool keep = (kg <= qg) && (kmsk[c0 + j] != 0);
                if (!keep) s[i][j] = NEG_BIG;
                mx = fmaxf(mx, s[i][j]);
            }
            #pragma unroll
            for (int off = 8; off >= 1; off >>= 1)
                mx = fmaxf(mx, __shfl_xor_sync(0xffffffffu, mx, off, 16));
            float mnew = fmaxf(m_[i], mx);
            alpha[i] = expf(m_[i] - mnew);
            float ls = 0.f;
            #pragma unroll
            for (int j = 0; j < 4; j++) {
                s[i][j] = expf(s[i][j] - mnew);
                ls += s[i][j];
            }
            #pragma unroll
            for (int off = 8; off >= 1; off >>= 1)
                ls += __shfl_xor_sync(0xffffffffu, ls, off, 16);
            l_[i] = l_[i] * alpha[i] + ls;
            m_[i] = mnew;
        }

        __syncthreads();
        #pragma unroll
        for (int i = 0; i < 4; i++)
            #pragma unroll
            for (int j = 0; j < 4; j++)
                KPs[(r0 + i) * 65 + c0 + j] = s[i][j];
        __syncthreads();

        #pragma unroll
        for (int i = 0; i < 4; i++)
            #pragma unroll
            for (int j = 0; j < 4; j++)
                acc[i][j] *= alpha[i];
        for (int kk = 0; kk < 64; kk++) {
            float pv[4], vv[4];
            #pragma unroll
            for (int i = 0; i < 4; i++) pv[i] = KPs[(r0 + i) * 65 + kk];
            #pragma unroll
            for (int j = 0; j < 4; j++) vv[j] = Vs[kk * 65 + c0 + j];
            #pragma unroll
            for (int i = 0; i < 4; i++)
                #pragma unroll
                for (int j = 0; j < 4; j++)
                    acc[i][j] = fmaf(pv[i], vv[j], acc[i][j]);
        }
    }

    #pragma unroll
    for (int i = 0; i < 4; i++) {
        float invl = 1.0f / l_[i];
        int qg = qt * 64 + r0 + i;
        #pragma unroll
        for (int j = 0; j < 4; j++)
            O[((size_t)(b * L_ + qg)) * D_ + h * DH + c0 + j] = acc[i][j] * invl;
    }
}

// ---------------- launch ------------------------------------------------
extern "C" void kernel_launch(void* const* d_in, const int* in_sizes, int n_in,
                              void* d_out, int out_size) {
    const float* x     = (const float*)d_in[0];
    const float* Wqkv  = (const float*)d_in[1];
    const float* bqkv  = (const float*)d_in[2];
    const float* Wproj = (const float*)d_in[3];
    const float* bproj = (const float*)d_in[4];
    const int*   mask  = (const int*)d_in[5];
    float* out = (float*)d_out;

    float *qkv, *q, *k, *v, *att;
    __nv_bfloat16 *ahi, *alo, *wqhi, *wqlo, *wphi, *wplo;
    cudaGetSymbolAddress((void**)&qkv,  g_qkv);
    cudaGetSymbolAddress((void**)&q,    g_q);
    cudaGetSymbolAddress((void**)&k,    g_k);
    cudaGetSymbolAddress((void**)&v,    g_v);
    cudaGetSymbolAddress((void**)&att,  g_att);
    cudaGetSymbolAddress((void**)&ahi,  g_ahi);
    cudaGetSymbolAddress((void**)&alo,  g_alo);
    cudaGetSymbolAddress((void**)&wqhi, g_wqhi);
    cudaGetSymbolAddress((void**)&wqlo, g_wqlo);
    cudaGetSymbolAddress((void**)&wphi, g_wphi);
    cudaGetSymbolAddress((void**)&wplo, g_wplo);

    int attn_smem = (3 * 64 * 65 + 64) * (int)sizeof(float);   // 50176 B
    cudaFuncSetAttribute(attn_kernel,
                         cudaFuncAttributeMaxDynamicSharedMemorySize, attn_smem);
    cudaFuncSetAttribute(gemm_bf16_kernel,
                         cudaFuncAttributeMaxDynamicSharedMemorySize, GEMM_SMEM);

    // 1) RoPE table
    rope_table_kernel<<<(L_ * 32) / 256, 256>>>();

    // 2) operand conversions for QKV GEMM
    convert_split_kernel<<<(int)(ML * D_ / 4 / 256), 256>>>(x, ahi, alo);
    transpose_split_kernel<<<dim3(D_ / 32, 3 * D_ / 32), dim3(32, 8)>>>(
        Wqkv, wqhi, wqlo, D_, 3 * D_);
    transpose_split_kernel<<<dim3(D_ / 32, D_ / 32), dim3(32, 8)>>>(
        Wproj, wphi, wplo, D_, D_);

    // 3) QKV GEMM: [8192,1024] x [1024,3072] on mma.sync bf16 split
    gemm_bf16_kernel<<<dim3(3 * D_ / 128, (int)(ML / 128)), 256, GEMM_SMEM>>>(
        ahi, alo, wqhi, wqlo, bqkv, qkv, 3 * D_, D_);

    // 4) split + RoPE -> [B,H,L,Dh]
    rope_split_kernel<<<(B_ * L_ * H_ * 32) / 256, 256>>>(qkv, q, k, v);

    // 5) causal flash attention -> [B,L,D]
    attn_kernel<<<dim3(L_ / 64, B_ * H_), 256, attn_smem>>>(q, k, v, mask, att);

    // 6) convert attention output, then output projection
    convert_split_kernel<<<(int)(ML * D_ / 4 / 256), 256>>>(att, ahi, alo);
    gemm_bf16_kernel<<<dim3(D_ / 128, (int)(ML / 128)), 256, GEMM_SMEM>>>(
        ahi, alo, wphi, wplo, bproj, out, D_, D_);
}

// round 10
// speedup vs baseline: 2.6943x; 1.8945x over previous
#include <cuda_runtime.h>
#include <cuda_bf16.h>
#include <cuda_fp16.h>
#include <math.h>
#include <stdint.h>

#define B_  4
#define L_  2048
#define D_  1024
#define H_  16
#define DH  64
#define ML  ((size_t)B_ * L_)          // 8192 rows

// ---------------- scratch (no allocation allowed) ----------------
__device__ float g_qkv[ML * 3 * D_];   // 8192 x 3072
__device__ float g_cos[L_ * 32];
__device__ float g_sin[L_ * 32];
// bf16 hi/lo operand buffers for tensor-core GEMMs
__device__ __nv_bfloat16 g_ahi[ML * D_];        // A (x, then att) hi
__device__ __nv_bfloat16 g_alo[ML * D_];        // A lo
__device__ __nv_bfloat16 g_wqhi[3 * D_ * D_];   // W_qkv^T hi  [3D, D]
__device__ __nv_bfloat16 g_wqlo[3 * D_ * D_];
__device__ __nv_bfloat16 g_wphi[D_ * D_];       // W_proj^T hi [D, D]
__device__ __nv_bfloat16 g_wplo[D_ * D_];
// fp16 attention operands
__device__ __half g_qh [ML * D_];      // Q hi (x0.125)  [bh][l][64]
__device__ __half g_ql [ML * D_];      // Q lo
__device__ __half g_kh [ML * D_];      // K single       [bh][l][64]
__device__ __half g_vth[ML * D_];      // V^T hi         [bh][dh][L]
__device__ __half g_vtl[ML * D_];      // V^T lo

// ================= helpers =================
__device__ __forceinline__ uint32_t smem_u32(const void* p) {
    uint32_t a;
    asm("{ .reg .u64 t; cvta.to.shared.u64 t, %1; cvt.u32.u64 %0, t; }" : "=r"(a) : "l"(p));
    return a;
}
__device__ __forceinline__ void cp_async16(uint32_t smaddr, const void* gaddr) {
    asm volatile("cp.async.cg.shared.global [%0], [%1], 16;" :: "r"(smaddr), "l"(gaddr));
}
#define CP_COMMIT() asm volatile("cp.async.commit_group;" ::: "memory")
#define CP_WAIT(n)  asm volatile("cp.async.wait_group %0;" :: "n"(n) : "memory")

__device__ __forceinline__ void ldmx4(uint32_t* r, uint32_t addr) {
    asm volatile("ldmatrix.sync.aligned.m8n8.x4.shared.b16 {%0,%1,%2,%3}, [%4];"
        : "=r"(r[0]), "=r"(r[1]), "=r"(r[2]), "=r"(r[3]) : "r"(addr));
}
__device__ __forceinline__ void mma_bf16(float* d, const uint32_t* a, const uint32_t* b) {
    asm volatile("mma.sync.aligned.m16n8k16.row.col.f32.bf16.bf16.f32 "
        "{%0,%1,%2,%3}, {%4,%5,%6,%7}, {%8,%9}, {%0,%1,%2,%3};"
        : "+f"(d[0]), "+f"(d[1]), "+f"(d[2]), "+f"(d[3])
        : "r"(a[0]), "r"(a[1]), "r"(a[2]), "r"(a[3]), "r"(b[0]), "r"(b[1]));
}
__device__ __forceinline__ void mma_f16(float* d, const uint32_t* a, const uint32_t* b) {
    asm volatile("mma.sync.aligned.m16n8k16.row.col.f32.f16.f16.f32 "
        "{%0,%1,%2,%3}, {%4,%5,%6,%7}, {%8,%9}, {%0,%1,%2,%3};"
        : "+f"(d[0]), "+f"(d[1]), "+f"(d[2]), "+f"(d[3])
        : "r"(a[0]), "r"(a[1]), "r"(a[2]), "r"(a[3]), "r"(b[0]), "r"(b[1]));
}
__device__ __forceinline__ uint32_t packh2(float a, float b) {
    __half2 h = __floats2half2_rn(a, b);
    return *reinterpret_cast<uint32_t*>(&h);
}

// ---------------- RoPE table (double-accurate, matches numpy f32 path) ---
__global__ void rope_table_kernel() {
    int idx = blockIdx.x * blockDim.x + threadIdx.x;   // L_*32 = 65536
    int i = idx & 31;
    int l = idx >> 5;
    double invd = exp(-(double)i * (9.210340371976184 / 32.0));
    float invf = (float)invd;
    float freq = (float)l * invf;
    g_cos[idx] = (float)cos((double)freq);
    g_sin[idx] = (float)sin((double)freq);
}

// ---------------- fp32 -> bf16 hi/lo split (elementwise) ----------------
__global__ void convert_split_kernel(const float* __restrict__ in,
    __nv_bfloat16* __restrict__ hi, __nv_bfloat16* __restrict__ lo)
{
    int i = blockIdx.x * blockDim.x + threadIdx.x;    // n/4 threads
    float4 v = ((const float4*)in)[i];
    __nv_bfloat16 h0 = __float2bfloat16(v.x);
    __nv_bfloat16 h1 = __float2bfloat16(v.y);
    __nv_bfloat16 h2 = __float2bfloat16(v.z);
    __nv_bfloat16 h3 = __float2bfloat16(v.w);
    __nv_bfloat16 l0 = __float2bfloat16(v.x - __bfloat162float(h0));
    __nv_bfloat16 l1 = __float2bfloat16(v.y - __bfloat162float(h1));
    __nv_bfloat16 l2 = __float2bfloat16(v.z - __bfloat162float(h2));
    __nv_bfloat16 l3 = __float2bfloat16(v.w - __bfloat162float(h3));
    __nv_bfloat162 hp0; hp0.x = h0; hp0.y = h1;
    __nv_bfloat162 hp1; hp1.x = h2; hp1.y = h3;
    __nv_bfloat162 lp0; lp0.x = l0; lp0.y = l1;
    __nv_bfloat162 lp1; lp1.x = l2; lp1.y = l3;
    ((__nv_bfloat162*)hi)[2 * i] = hp0;
    ((__nv_bfloat162*)hi)[2 * i + 1] = hp1;
    ((__nv_bfloat162*)lo)[2 * i] = lp0;
    ((__nv_bfloat162*)lo)[2 * i + 1] = lp1;
}

// ---------------- W [K,N] fp32 -> W^T [N,K] bf16 hi/lo ------------------
__global__ void transpose_split_kernel(const float* __restrict__ W,
    __nv_bfloat16* __restrict__ Thi, __nv_bfloat16* __restrict__ Tlo, int Kd, int Nd)
{
    __shared__ float t[32][33];
    int k0 = blockIdx.x * 32, n0 = blockIdx.y * 32;
    int tx = threadIdx.x, ty = threadIdx.y;
    #pragma unroll
    for (int r = ty; r < 32; r += 8)
        t[r][tx] = W[(size_t)(k0 + r) * Nd + n0 + tx];
    __syncthreads();
    #pragma unroll
    for (int r = ty; r < 32; r += 8) {
        float v = t[tx][r];
        __nv_bfloat16 h = __float2bfloat16(v);
        __nv_bfloat16 l = __float2bfloat16(v - __bfloat162float(h));
        size_t o = (size_t)(n0 + r) * Kd + k0 + tx;
        Thi[o] = h;
        Tlo[o] = l;
    }
}

// ---------------- mma.sync bf16 split GEMM (unchanged, validated) -------
#define T_STRIDE 80
#define T_BYTES  (128 * T_STRIDE)      // 10240
#define BUF_BYTES (4 * T_BYTES)        // 40960
#define GEMM_SMEM (2 * BUF_BYTES)      // 81920

__global__ __launch_bounds__(256, 1) void gemm_bf16_kernel(
    const __nv_bfloat16* __restrict__ Ahi, const __nv_bfloat16* __restrict__ Alo,
    const __nv_bfloat16* __restrict__ Bhi, const __nv_bfloat16* __restrict__ Blo,
    const float* __restrict__ bias, float* __restrict__ C, int N, int K)
{
    extern __shared__ char smraw[];
    const uint32_t smb = smem_u32(smraw);
    const int tid = threadIdx.x;
    const int wid = tid >> 5, lane = tid & 31;
    const int wr = wid & 1, wc = wid >> 1;
    const int bn = blockIdx.x * 128, bm = blockIdx.y * 128;

    const char* gp[4];
    gp[0] = (const char*)(Ahi + (size_t)bm * K);
    gp[1] = (const char*)(Alo + (size_t)bm * K);
    gp[2] = (const char*)(Bhi + (size_t)bn * K);
    gp[3] = (const char*)(Blo + (size_t)bn * K);

    const int NKB = K / 32;

    auto issue_loads = [&](int kb, int buf) {
        uint32_t sbase = smb + buf * BUF_BYTES;
        #pragma unroll
        for (int op = 0; op < 4; op++) {
            #pragma unroll
            for (int half = 0; half < 2; half++) {
                int idx = half * 256 + tid;          // 0..511
                int row = idx >> 2, c = idx & 3;
                const void* g = gp[op] + ((size_t)row * K + kb * 32 + c * 8) * 2;
                uint32_t s = sbase + op * T_BYTES + row * T_STRIDE + c * 16;
                cp_async16(s, g);
            }
        }
    };

    float acc[4][4][4];
    #pragma unroll
    for (int i = 0; i < 4; i++)
        #pragma unroll
        for (int j = 0; j < 4; j++)
            #pragma unroll
            for (int r = 0; r < 4; r++) acc[i][j][r] = 0.f;

    issue_loads(0, 0);
    CP_COMMIT();

    const int lr = lane & 15, lh = lane >> 4;
    const int bj = lane >> 4, bch = (lane >> 3) & 1, bn8 = lane & 7;

    for (int kb = 0; kb < NKB; kb++) {
        int buf = kb & 1;
        if (kb + 1 < NKB) { issue_loads(kb + 1, buf ^ 1); CP_COMMIT(); CP_WAIT(1); }
        else             { CP_WAIT(0); }
        __syncthreads();

        uint32_t sA_hi = smb + buf * BUF_BYTES;
        uint32_t sA_lo = sA_hi + T_BYTES;
        uint32_t sB_hi = sA_hi + 2 * T_BYTES;
        uint32_t sB_lo = sA_hi + 3 * T_BYTES;

        #pragma unroll
        for (int s = 0; s < 2; s++) {
            uint32_t ahi[4][4], alo[4][4], bhi[4][2], blo[4][2];
            #pragma unroll
            for (int i = 0; i < 4; i++) {
                uint32_t off = (uint32_t)((wr * 64 + i * 16 + lr) * T_STRIDE + (s * 2 + lh) * 16);
                ldmx4(ahi[i], sA_hi + off);
                ldmx4(alo[i], sA_lo + off);
            }
            #pragma unroll
            for (int jp = 0; jp < 2; jp++) {
                uint32_t tmp[4];
                uint32_t off = (uint32_t)((wc * 32 + (2 * jp + bj) * 8 + bn8) * T_STRIDE
                                          + (s * 2 + bch) * 16);
                ldmx4(tmp, sB_hi + off);
                bhi[2 * jp][0] = tmp[0]; bhi[2 * jp][1] = tmp[1];
                bhi[2 * jp + 1][0] = tmp[2]; bhi[2 * jp + 1][1] = tmp[3];
                ldmx4(tmp, sB_lo + off);
                blo[2 * jp][0] = tmp[0]; blo[2 * jp][1] = tmp[1];
                blo[2 * jp + 1][0] = tmp[2]; blo[2 * jp + 1][1] = tmp[3];
            }
            #pragma unroll
            for (int i = 0; i < 4; i++)
                #pragma unroll
                for (int j = 0; j < 4; j++) {
                    mma_bf16(acc[i][j], ahi[i], bhi[j]);
                    mma_bf16(acc[i][j], ahi[i], blo[j]);
                    mma_bf16(acc[i][j], alo[i], bhi[j]);
                }
        }
        __syncthreads();
    }

    #pragma unroll
    for (int i = 0; i < 4; i++) {
        int row = bm + wr * 64 + i * 16 + (lane >> 2);
        #pragma unroll
        for (int j = 0; j < 4; j++) {
            int col = bn + wc * 32 + j * 8 + 2 * (lane & 3);
            float b0 = bias[col], b1 = bias[col + 1];
            float2 o0; o0.x = acc[i][j][0] + b0; o0.y = acc[i][j][1] + b1;
            float2 o1; o1.x = acc[i][j][2] + b0; o1.y = acc[i][j][3] + b1;
            *(float2*)(C + (size_t)row * N + col) = o0;
            *(float2*)(C + (size_t)(row + 8) * N + col) = o1;
        }
    }
}

// ---------------- split qkv + RoPE -> fp16 attention operands ----------
// Qh/Ql: Q*0.125 hi/lo fp16 [bh][l][64]; Kh single fp16 [bh][l][64];
// Vth/Vtl: V^T hi/lo fp16 [bh][dh][L].
__global__ void rope_split_fp16_kernel(const float* __restrict__ qkv,
    __half* __restrict__ Qh, __half* __restrict__ Ql, __half* __restrict__ Kh,
    __half* __restrict__ Vth, __half* __restrict__ Vtl)
{
    int idx = blockIdx.x * blockDim.x + threadIdx.x;   // B*L*H*32 = 2^22
    int i = idx & 31;
    int h = (idx >> 5) & 15;
    int l = (idx >> 9) & 2047;
    int b = idx >> 20;
    int bh = b * H_ + h;
    const float* base = qkv + ((size_t)(b * L_ + l)) * (3 * D_) + h * DH;
    float c = g_cos[l * 32 + i];
    float s = g_sin[l * 32 + i];
    float q1 = base[2 * i],        q2 = base[2 * i + 1];
    float k1 = base[D_ + 2 * i],   k2 = base[D_ + 2 * i + 1];
    float v1 = base[2 * D_ + 2 * i], v2 = base[2 * D_ + 2 * i + 1];
    float qr1 = (q1 * c - q2 * s) * 0.125f;
    float qr2 = (q1 * s + q2 * c) * 0.125f;
    float kr1 = k1 * c - k2 * s;
    float kr2 = k1 * s + k2 * c;

    size_t o = ((size_t)(bh * L_ + l)) * DH + 2 * i;
    __half qh1 = __float2half(qr1), qh2 = __float2half(qr2);
    __half2 qhp; qhp.x = qh1; qhp.y = qh2;
    __half2 qlp; qlp.x = __float2half(qr1 - __half2float(qh1));
                 qlp.y = __float2half(qr2 - __half2float(qh2));
    *(__half2*)(Qh + o) = qhp;
    *(__half2*)(Ql + o) = qlp;
    __half2 khp; khp.x = __float2half(kr1); khp.y = __float2half(kr2);
    *(__half2*)(Kh + o) = khp;

    // V transposed, hi/lo
    __half vh1 = __float2half(v1), vh2 = __float2half(v2);
    size_t ot1 = ((size_t)(bh * DH + 2 * i)) * L_ + l;
    size_t ot2 = ((size_t)(bh * DH + 2 * i + 1)) * L_ + l;
    Vth[ot1] = vh1;
    Vth[ot2] = vh2;
    Vtl[ot1] = __float2half(v1 - __half2float(vh1));
    Vtl[ot2] = __float2half(v2 - __half2float(vh2));
}

// ---------------- tensor-core causal flash attention --------------------
// block: 128 q-rows (8 warps x m16), kv tiles of 64. fp16 mma, fp32 softmax.
// S = (Qhi+Qlo) K^T (2 mma/tile), O += P (Vhi+Vlo) (2 mma/tile).
// Writes bf16 hi/lo of output directly into proj-GEMM A buffers.
#define AT_STRIDE 144
#define AT_KT  (64 * AT_STRIDE)       // 9216
#define AT_BUF (3 * AT_KT)            // K, Vh, Vl = 27648
#define AT_SMEM (2 * AT_BUF + 512)    // + 2 kbias slots

__global__ __launch_bounds__(256, 1) void attn_mma_kernel(
    const __half* __restrict__ Qh, const __half* __restrict__ Ql,
    const __half* __restrict__ Kh,
    const __half* __restrict__ Vth, const __half* __restrict__ Vtl,
    const int* __restrict__ mask,
    __nv_bfloat16* __restrict__ Ohi, __nv_bfloat16* __restrict__ Olo)
{
    extern __shared__ char sm[];
    const uint32_t smb = smem_u32(sm);
    const int tid = threadIdx.x, lane = tid & 31, w = tid >> 5;
    const int qt = 15 - (int)blockIdx.y;        // heavy blocks first
    const int bh = blockIdx.x;
    const int b = bh >> 4, h = bh & 15;
    const int qrow0 = qt * 128 + w * 16;

    // ---- stage Q tile into smem, move to register fragments ----
    {
        const __half* s0 = Qh + ((size_t)bh * L_ + qt * 128) * DH;
        const __half* s1 = Ql + ((size_t)bh * L_ + qt * 128) * DH;
        #pragma unroll
        for (int c2 = 0; c2 < 4; c2++) {
            int idx = c2 * 256 + tid;            // 0..1023
            int row = idx >> 3, c = idx & 7;
            cp_async16(smb + row * AT_STRIDE + c * 16, s0 + (size_t)row * DH + c * 8);
            cp_async16(smb + 128 * AT_STRIDE + row * AT_STRIDE + c * 16,
                       s1 + (size_t)row * DH + c * 8);
        }
        CP_COMMIT(); CP_WAIT(0);
        __syncthreads();
    }
    uint32_t qfh[4][4], qfl[4][4];
    {
        const int lr = lane & 15, lhh = lane >> 4;
        #pragma unroll
        for (int kt = 0; kt < 4; kt++) {
            uint32_t off = (uint32_t)((w * 16 + lr) * AT_STRIDE + (kt * 2 + lhh) * 16);
            ldmx4(qfh[kt], smb + off);
            ldmx4(qfl[kt], smb + 128 * AT_STRIDE + off);
        }
    }
    __syncthreads();

    const __half* kg  = Kh  + (size_t)bh * L_ * DH;
    const __half* vhg = Vth + (size_t)bh * DH * L_;
    const __half* vlg = Vtl + (size_t)bh * DH * L_;
    const int* mp = mask + b * L_;

    auto issue = [&](int t, int buf) {
        uint32_t base = smb + buf * AT_BUF;
        int k0 = t * 64;
        #pragma unroll
        for (int hf = 0; hf < 2; hf++) {
            int idx = hf * 256 + tid;            // 0..511
            int row = idx >> 3, c = idx & 7;
            cp_async16(base + row * AT_STRIDE + c * 16,
                       kg + ((size_t)(k0 + row)) * DH + c * 8);
            cp_async16(base + AT_KT + row * AT_STRIDE + c * 16,
                       vhg + (size_t)row * L_ + k0 + c * 8);
            cp_async16(base + 2 * AT_KT + row * AT_STRIDE + c * 16,
                       vlg + (size_t)row * L_ + k0 + c * 8);
        }
        if (tid < 64)
            *(float*)(sm + 2 * AT_BUF + buf * 256 + tid * 4) =
                mp[k0 + tid] ? 0.f : -1e30f;
    };

    float oa[8][4];
    #pragma unroll
    for (int j = 0; j < 8; j++)
        #pragma unroll
        for (int r = 0; r < 4; r++) oa[j][r] = 0.f;
    float m0 = -1e30f, m1 = -1e30f, l0 = 0.f, l1 = 0.f;

    const int nt = (qt + 1) * 2;
    const int bjj = lane >> 4, bch = (lane >> 3) & 1, bn8 = lane & 7;
    const int t4 = (lane & 3) * 2;
    const int rg = lane >> 2;

    issue(0, 0); CP_COMMIT();
    for (int t = 0; t < nt; t++) {
        int buf = t & 1;
        if (t + 1 < nt) { issue(t + 1, buf ^ 1); CP_COMMIT(); CP_WAIT(1); }
        else            { CP_WAIT(0); }
        __syncthreads();

        uint32_t kbase = smb + buf * AT_BUF;
        const float* kbias = (const float*)(sm + 2 * AT_BUF + buf * 256);
        int k0 = t * 64;

        // ---- S = Q K^T ----
        float sa[8][4];
        #pragma unroll
        for (int j = 0; j < 8; j++)
            #pragma unroll
            for (int r = 0; r < 4; r++) sa[j][r] = 0.f;
        #pragma unroll
        for (int jp = 0; jp < 4; jp++) {
            #pragma unroll
            for (int kt = 0; kt < 4; kt++) {
                uint32_t tmp[4];
                ldmx4(tmp, kbase + (uint32_t)(((2 * jp + bjj) * 8 + bn8) * AT_STRIDE
                                              + (kt * 2 + bch) * 16));
                mma_f16(sa[2 * jp],     qfh[kt], tmp);
                mma_f16(sa[2 * jp],     qfl[kt], tmp);
                mma_f16(sa[2 * jp + 1], qfh[kt], tmp + 2);
                mma_f16(sa[2 * jp + 1], qfl[kt], tmp + 2);
            }
        }

        // ---- key bias + causal mask ----
        #pragma unroll
        for (int j = 0; j < 8; j++) {
            float2 kb = *(const float2*)&kbias[j * 8 + t4];
            sa[j][0] += kb.x; sa[j][1] += kb.y;
            sa[j][2] += kb.x; sa[j][3] += kb.y;
        }
        if (k0 + 63 > qrow0) {
            int r0 = qrow0 + rg;
            #pragma unroll
            for (int j = 0; j < 8; j++) {
                int cc = k0 + j * 8 + t4;
                if (cc     > r0)     sa[j][0] = -1e30f;
                if (cc + 1 > r0)     sa[j][1] = -1e30f;
                if (cc     > r0 + 8) sa[j][2] = -1e30f;
                if (cc + 1 > r0 + 8) sa[j][3] = -1e30f;
            }
        }

        // ---- online softmax ----
        float mx0 = -1e30f, mx1 = -1e30f;
        #pragma unroll
        for (int j = 0; j < 8; j++) {
            mx0 = fmaxf(mx0, fmaxf(sa[j][0], sa[j][1]));
            mx1 = fmaxf(mx1, fmaxf(sa[j][2], sa[j][3]));
        }
        mx0 = fmaxf(mx0, __shfl_xor_sync(0xffffffffu, mx0, 1));
        mx0 = fmaxf(mx0, __shfl_xor_sync(0xffffffffu, mx0, 2));
        mx1 = fmaxf(mx1, __shfl_xor_sync(0xffffffffu, mx1, 1));
        mx1 = fmaxf(mx1, __shfl_xor_sync(0xffffffffu, mx1, 2));
        float mn0 = fmaxf(m0, mx0), mn1 = fmaxf(m1, mx1);
        float a0 = __expf(m0 - mn0), a1 = __expf(m1 - mn1);
        m0 = mn0; m1 = mn1;
        float s0 = 0.f, s1 = 0.f;
        #pragma unroll
        for (int j = 0; j < 8; j++) {
            sa[j][0] = __expf(sa[j][0] - mn0);
            sa[j][1] = __expf(sa[j][1] - mn0);
            sa[j][2] = __expf(sa[j][2] - mn1);
            sa[j][3] = __expf(sa[j][3] - mn1);
            s0 += sa[j][0] + sa[j][1];
            s1 += sa[j][2] + sa[j][3];
        }
        s0 += __shfl_xor_sync(0xffffffffu, s0, 1);
        s0 += __shfl_xor_sync(0xffffffffu, s0, 2);
        s1 += __shfl_xor_sync(0xffffffffu, s1, 1);
        s1 += __shfl_xor_sync(0xffffffffu, s1, 2);
        l0 = l0 * a0 + s0;
        l1 = l1 * a1 + s1;

        // ---- P fragments (fp16) ----
        uint32_t pf[4][4];
        #pragma unroll
        for (int kt = 0; kt < 4; kt++) {
            pf[kt][0] = packh2(sa[2 * kt][0],     sa[2 * kt][1]);
            pf[kt][1] = packh2(sa[2 * kt][2],     sa[2 * kt][3]);
            pf[kt][2] = packh2(sa[2 * kt + 1][0], sa[2 * kt + 1][1]);
            pf[kt][3] = packh2(sa[2 * kt + 1][2], sa[2 * kt + 1][3]);
        }

        // ---- O = O*alpha + P V ----
        #pragma unroll
        for (int j = 0; j < 8; j++) {
            oa[j][0] *= a0; oa[j][1] *= a0;
            oa[j][2] *= a1; oa[j][3] *= a1;
        }
        uint32_t vhb = kbase + AT_KT, vlb = kbase + 2 * AT_KT;
        #pragma unroll
        for (int jp = 0; jp < 4; jp++) {
            #pragma unroll
            for (int kt = 0; kt < 4; kt++) {
                uint32_t off = (uint32_t)(((2 * jp + bjj) * 8 + bn8) * AT_STRIDE
                                          + (kt * 2 + bch) * 16);
                uint32_t tv[4];
                ldmx4(tv, vhb + off);
                mma_f16(oa[2 * jp],     pf[kt], tv);
                mma_f16(oa[2 * jp + 1], pf[kt], tv + 2);
                ldmx4(tv, vlb + off);
                mma_f16(oa[2 * jp],     pf[kt], tv);
                mma_f16(oa[2 * jp + 1], pf[kt], tv + 2);
            }
        }
        __syncthreads();
    }

    // ---- epilogue: bf16 hi/lo split straight into proj-GEMM A buffers ----
    float i0 = 1.f / l0, i1 = 1.f / l1;
    int r0 = qrow0 + rg;
    #pragma unroll
    for (int j = 0; j < 8; j++) {
        int col = h * DH + j * 8 + t4;
        float x0 = oa[j][0] * i0, x1 = oa[j][1] * i0;
        float y0 = oa[j][2] * i1, y1 = oa[j][3] * i1;
        __nv_bfloat16 xh0 = __float2bfloat16(x0), xh1 = __float2bfloat16(x1);
        __nv_bfloat16 yh0 = __float2bfloat16(y0), yh1 = __float2bfloat16(y1);
        __nv_bfloat162 xh; xh.x = xh0; xh.y = xh1;
        __nv_bfloat162 xl; xl.x = __float2bfloat16(x0 - __bfloat162float(xh0));
                           xl.y = __float2bfloat16(x1 - __bfloat162float(xh1));
        __nv_bfloat162 yh; yh.x = yh0; yh.y = yh1;
        __nv_bfloat162 yl; yl.x = __float2bfloat16(y0 - __bfloat162float(yh0));
                           yl.y = __float2bfloat16(y1 - __bfloat162float(yh1));
        size_t ro0 = ((size_t)(b * L_ + r0)) * D_ + col;
        size_t ro1 = ((size_t)(b * L_ + r0 + 8)) * D_ + col;
        *(__nv_bfloat162*)(Ohi + ro0) = xh;
        *(__nv_bfloat162*)(Olo + ro0) = xl;
        *(__nv_bfloat162*)(Ohi + ro1) = yh;
        *(__nv_bfloat162*)(Olo + ro1) = yl;
    }
}

// ---------------- launch ------------------------------------------------
extern "C" void kernel_launch(void* const* d_in, const int* in_sizes, int n_in,
                              void* d_out, int out_size) {
    const float* x     = (const float*)d_in[0];
    const float* Wqkv  = (const float*)d_in[1];
    const float* bqkv  = (const float*)d_in[2];
    const float* Wproj = (const float*)d_in[3];
    const float* bproj = (const float*)d_in[4];
    const int*   mask  = (const int*)d_in[5];
    float* out = (float*)d_out;

    float *qkv;
    __nv_bfloat16 *ahi, *alo, *wqhi, *wqlo, *wphi, *wplo;
    __half *qh, *ql, *kh, *vth, *vtl;
    cudaGetSymbolAddress((void**)&qkv,  g_qkv);
    cudaGetSymbolAddress((void**)&ahi,  g_ahi);
    cudaGetSymbolAddress((void**)&alo,  g_alo);
    cudaGetSymbolAddress((void**)&wqhi, g_wqhi);
    cudaGetSymbolAddress((void**)&wqlo, g_wqlo);
    cudaGetSymbolAddress((void**)&wphi, g_wphi);
    cudaGetSymbolAddress((void**)&wplo, g_wplo);
    cudaGetSymbolAddress((void**)&qh,   g_qh);
    cudaGetSymbolAddress((void**)&ql,   g_ql);
    cudaGetSymbolAddress((void**)&kh,   g_kh);
    cudaGetSymbolAddress((void**)&vth,  g_vth);
    cudaGetSymbolAddress((void**)&vtl,  g_vtl);

    cudaFuncSetAttribute(gemm_bf16_kernel,
                         cudaFuncAttributeMaxDynamicSharedMemorySize, GEMM_SMEM);
    cudaFuncSetAttribute(attn_mma_kernel,
                         cudaFuncAttributeMaxDynamicSharedMemorySize, AT_SMEM);

    // 1) RoPE table
    rope_table_kernel<<<(L_ * 32) / 256, 256>>>();

    // 2) operand conversions for QKV GEMM
    convert_split_kernel<<<(int)(ML * D_ / 4 / 256), 256>>>(x, ahi, alo);
    transpose_split_kernel<<<dim3(D_ / 32, 3 * D_ / 32), dim3(32, 8)>>>(
        Wqkv, wqhi, wqlo, D_, 3 * D_);
    transpose_split_kernel<<<dim3(D_ / 32, D_ / 32), dim3(32, 8)>>>(
        Wproj, wphi, wplo, D_, D_);

    // 3) QKV GEMM: [8192,1024] x [1024,3072] on mma.sync bf16 split
    gemm_bf16_kernel<<<dim3(3 * D_ / 128, (int)(ML / 128)), 256, GEMM_SMEM>>>(
        ahi, alo, wqhi, wqlo, bqkv, qkv, 3 * D_, D_);

    // 4) split + RoPE -> fp16 attention operands
    rope_split_fp16_kernel<<<(B_ * L_ * H_ * 32) / 256, 256>>>(
        qkv, qh, ql, kh, vth, vtl);

    // 5) tensor-core causal flash attention -> bf16 hi/lo proj operands
    attn_mma_kernel<<<dim3(B_ * H_, L_ / 128), 256, AT_SMEM>>>(
        qh, ql, kh, vth, vtl, mask, ahi, alo);

    // 6) output projection on mma.sync bf16 split
    gemm_bf16_kernel<<<dim3(D_ / 128, (int)(ML / 128)), 256, GEMM_SMEM>>>(
        ahi, alo, wphi, wplo, bproj, out, D_, D_);
}

// round 11
// speedup vs baseline: 3.0782x; 1.1425x over previous
#include <cuda_runtime.h>
#include <cuda_bf16.h>
#include <cuda_fp16.h>
#include <math.h>
#include <stdint.h>

#define B_  4
#define L_  2048
#define D_  1024
#define H_  16
#define DH  64
#define ML  ((size_t)B_ * L_)          // 8192 rows

// ---------------- scratch (no allocation allowed) ----------------
__device__ float g_cos[L_ * 32];
__device__ float g_sin[L_ * 32];
// bf16 hi/lo operand buffers for tensor-core GEMMs
__device__ __nv_bfloat16 g_ahi[ML * D_];        // A (x, then att) hi
__device__ __nv_bfloat16 g_alo[ML * D_];        // A lo
__device__ __nv_bfloat16 g_wqhi[3 * D_ * D_];   // W_qkv^T hi  [3D, D]
__device__ __nv_bfloat16 g_wqlo[3 * D_ * D_];
__device__ __nv_bfloat16 g_wphi[D_ * D_];       // W_proj^T hi [D, D]
__device__ __nv_bfloat16 g_wplo[D_ * D_];
// fp16 attention operands (all [bh][l][64] K-major)
__device__ __half g_qh[ML * D_];       // Q hi (x0.125)
__device__ __half g_ql[ML * D_];       // Q lo
__device__ __half g_kh[ML * D_];       // K single
__device__ __half g_vh[ML * D_];       // V hi
__device__ __half g_vl[ML * D_];       // V lo

// ================= helpers =================
__device__ __forceinline__ uint32_t smem_u32(const void* p) {
    uint32_t a;
    asm("{ .reg .u64 t; cvta.to.shared.u64 t, %1; cvt.u32.u64 %0, t; }" : "=r"(a) : "l"(p));
    return a;
}
__device__ __forceinline__ void cp_async16(uint32_t smaddr, const void* gaddr) {
    asm volatile("cp.async.cg.shared.global [%0], [%1], 16;" :: "r"(smaddr), "l"(gaddr));
}
#define CP_COMMIT() asm volatile("cp.async.commit_group;" ::: "memory")
#define CP_WAIT(n)  asm volatile("cp.async.wait_group %0;" :: "n"(n) : "memory")

__device__ __forceinline__ void ldmx4(uint32_t* r, uint32_t addr) {
    asm volatile("ldmatrix.sync.aligned.m8n8.x4.shared.b16 {%0,%1,%2,%3}, [%4];"
        : "=r"(r[0]), "=r"(r[1]), "=r"(r[2]), "=r"(r[3]) : "r"(addr));
}
__device__ __forceinline__ void ldmx4t(uint32_t* r, uint32_t addr) {
    asm volatile("ldmatrix.sync.aligned.m8n8.x4.trans.shared.b16 {%0,%1,%2,%3}, [%4];"
        : "=r"(r[0]), "=r"(r[1]), "=r"(r[2]), "=r"(r[3]) : "r"(addr));
}
__device__ __forceinline__ void mma_bf16(float* d, const uint32_t* a, const uint32_t* b) {
    asm volatile("mma.sync.aligned.m16n8k16.row.col.f32.bf16.bf16.f32 "
        "{%0,%1,%2,%3}, {%4,%5,%6,%7}, {%8,%9}, {%0,%1,%2,%3};"
        : "+f"(d[0]), "+f"(d[1]), "+f"(d[2]), "+f"(d[3])
        : "r"(a[0]), "r"(a[1]), "r"(a[2]), "r"(a[3]), "r"(b[0]), "r"(b[1]));
}
__device__ __forceinline__ void mma_f16(float* d, const uint32_t* a, const uint32_t* b) {
    asm volatile("mma.sync.aligned.m16n8k16.row.col.f32.f16.f16.f32 "
        "{%0,%1,%2,%3}, {%4,%5,%6,%7}, {%8,%9}, {%0,%1,%2,%3};"
        : "+f"(d[0]), "+f"(d[1]), "+f"(d[2]), "+f"(d[3])
        : "r"(a[0]), "r"(a[1]), "r"(a[2]), "r"(a[3]), "r"(b[0]), "r"(b[1]));
}
__device__ __forceinline__ uint32_t packh2(float a, float b) {
    __half2 h = __floats2half2_rn(a, b);
    return *reinterpret_cast<uint32_t*>(&h);
}

// ---------------- RoPE table (double-accurate, matches numpy f32 path) ---
__global__ void rope_table_kernel() {
    int idx = blockIdx.x * blockDim.x + threadIdx.x;   // L_*32 = 65536
    int i = idx & 31;
    int l = idx >> 5;
    double invd = exp(-(double)i * (9.210340371976184 / 32.0));
    float invf = (float)invd;
    float freq = (float)l * invf;
    g_cos[idx] = (float)cos((double)freq);
    g_sin[idx] = (float)sin((double)freq);
}

// ---------------- fp32 -> bf16 hi/lo split (elementwise) ----------------
__global__ void convert_split_kernel(const float* __restrict__ in,
    __nv_bfloat16* __restrict__ hi, __nv_bfloat16* __restrict__ lo)
{
    int i = blockIdx.x * blockDim.x + threadIdx.x;    // n/4 threads
    float4 v = ((const float4*)in)[i];
    __nv_bfloat16 h0 = __float2bfloat16(v.x);
    __nv_bfloat16 h1 = __float2bfloat16(v.y);
    __nv_bfloat16 h2 = __float2bfloat16(v.z);
    __nv_bfloat16 h3 = __float2bfloat16(v.w);
    __nv_bfloat162 hp0; hp0.x = h0; hp0.y = h1;
    __nv_bfloat162 hp1; hp1.x = h2; hp1.y = h3;
    __nv_bfloat162 lp0; lp0.x = __float2bfloat16(v.x - __bfloat162float(h0));
                        lp0.y = __float2bfloat16(v.y - __bfloat162float(h1));
    __nv_bfloat162 lp1; lp1.x = __float2bfloat16(v.z - __bfloat162float(h2));
                        lp1.y = __float2bfloat16(v.w - __bfloat162float(h3));
    ((__nv_bfloat162*)hi)[2 * i] = hp0;
    ((__nv_bfloat162*)hi)[2 * i + 1] = hp1;
    ((__nv_bfloat162*)lo)[2 * i] = lp0;
    ((__nv_bfloat162*)lo)[2 * i + 1] = lp1;
}

// ---------------- W [K,N] fp32 -> W^T [N,K] bf16 hi/lo ------------------
__global__ void transpose_split_kernel(const float* __restrict__ W,
    __nv_bfloat16* __restrict__ Thi, __nv_bfloat16* __restrict__ Tlo, int Kd, int Nd)
{
    __shared__ float t[32][33];
    int k0 = blockIdx.x * 32, n0 = blockIdx.y * 32;
    int tx = threadIdx.x, ty = threadIdx.y;
    #pragma unroll
    for (int r = ty; r < 32; r += 8)
        t[r][tx] = W[(size_t)(k0 + r) * Nd + n0 + tx];
    __syncthreads();
    #pragma unroll
    for (int r = ty; r < 32; r += 8) {
        float v = t[tx][r];
        __nv_bfloat16 h = __float2bfloat16(v);
        __nv_bfloat16 l = __float2bfloat16(v - __bfloat162float(h));
        size_t o = (size_t)(n0 + r) * Kd + k0 + tx;
        Thi[o] = h;
        Tlo[o] = l;
    }
}

// ---------------- mma.sync bf16 split GEMM, 3-stage pipeline ------------
// MODE 0: C = A*B^T + bias (fp32 out).  MODE 1: fused QKV epilogue:
// rope+scale+fp16-split, writes Qh/Ql/Kh/Vh/Vl directly.
#define T_STRIDE 80
#define T_BYTES  (128 * T_STRIDE)      // 10240
#define BUF_BYTES (4 * T_BYTES)        // 40960
#define GEMM_SMEM (3 * BUF_BYTES)      // 122880

template<int MODE>
__global__ __launch_bounds__(256, 1) void gemm_bf16_kernel(
    const __nv_bfloat16* __restrict__ Ahi, const __nv_bfloat16* __restrict__ Alo,
    const __nv_bfloat16* __restrict__ Bhi, const __nv_bfloat16* __restrict__ Blo,
    const float* __restrict__ bias, float* __restrict__ C, int N, int K,
    __half* __restrict__ Qh, __half* __restrict__ Ql, __half* __restrict__ Kh,
    __half* __restrict__ Vh, __half* __restrict__ Vl)
{
    extern __shared__ char smraw[];
    const uint32_t smb = smem_u32(smraw);
    const int tid = threadIdx.x;
    const int wid = tid >> 5, lane = tid & 31;
    const int wr = wid & 1, wc = wid >> 1;
    const int bn = blockIdx.x * 128, bm = blockIdx.y * 128;

    const char* gp[4];
    gp[0] = (const char*)(Ahi + (size_t)bm * K);
    gp[1] = (const char*)(Alo + (size_t)bm * K);
    gp[2] = (const char*)(Bhi + (size_t)bn * K);
    gp[3] = (const char*)(Blo + (size_t)bn * K);

    const int NKB = K / 32;            // 32

    auto issue_loads = [&](int kb, int buf) {
        uint32_t sbase = smb + buf * BUF_BYTES;
        #pragma unroll
        for (int op = 0; op < 4; op++) {
            #pragma unroll
            for (int half = 0; half < 2; half++) {
                int idx = half * 256 + tid;          // 0..511
                int row = idx >> 2, c = idx & 3;
                const void* g = gp[op] + ((size_t)row * K + kb * 32 + c * 8) * 2;
                uint32_t s = sbase + op * T_BYTES + row * T_STRIDE + c * 16;
                cp_async16(s, g);
            }
        }
    };

    float acc[4][4][4];
    #pragma unroll
    for (int i = 0; i < 4; i++)
        #pragma unroll
        for (int j = 0; j < 4; j++)
            #pragma unroll
            for (int r = 0; r < 4; r++) acc[i][j][r] = 0.f;

    issue_loads(0, 0); CP_COMMIT();
    issue_loads(1, 1); CP_COMMIT();

    const int lr = lane & 15, lh = lane >> 4;
    const int bj = lane >> 4, bch = (lane >> 3) & 1, bn8 = lane & 7;

    for (int kb = 0; kb < NKB; kb++) {
        if (kb + 1 < NKB) { CP_WAIT(1); } else { CP_WAIT(0); }
        __syncthreads();
        if (kb + 2 < NKB) { issue_loads(kb + 2, (kb + 2) % 3); CP_COMMIT(); }

        uint32_t sA_hi = smb + (kb % 3) * BUF_BYTES;
        uint32_t sA_lo = sA_hi + T_BYTES;
        uint32_t sB_hi = sA_hi + 2 * T_BYTES;
        uint32_t sB_lo = sA_hi + 3 * T_BYTES;

        #pragma unroll
        for (int s = 0; s < 2; s++) {
            uint32_t ahi[4][4], alo[4][4], bhi[4][2], blo[4][2];
            #pragma unroll
            for (int i = 0; i < 4; i++) {
                uint32_t off = (uint32_t)((wr * 64 + i * 16 + lr) * T_STRIDE + (s * 2 + lh) * 16);
                ldmx4(ahi[i], sA_hi + off);
                ldmx4(alo[i], sA_lo + off);
            }
            #pragma unroll
            for (int jp = 0; jp < 2; jp++) {
                uint32_t tmp[4];
                uint32_t off = (uint32_t)((wc * 32 + (2 * jp + bj) * 8 + bn8) * T_STRIDE
                                          + (s * 2 + bch) * 16);
                ldmx4(tmp, sB_hi + off);
                bhi[2 * jp][0] = tmp[0]; bhi[2 * jp][1] = tmp[1];
                bhi[2 * jp + 1][0] = tmp[2]; bhi[2 * jp + 1][1] = tmp[3];
                ldmx4(tmp, sB_lo + off);
                blo[2 * jp][0] = tmp[0]; blo[2 * jp][1] = tmp[1];
                blo[2 * jp + 1][0] = tmp[2]; blo[2 * jp + 1][1] = tmp[3];
            }
            #pragma unroll
            for (int i = 0; i < 4; i++)
                #pragma unroll
                for (int j = 0; j < 4; j++) {
                    mma_bf16(acc[i][j], ahi[i], bhi[j]);
                    mma_bf16(acc[i][j], ahi[i], blo[j]);
                    mma_bf16(acc[i][j], alo[i], bhi[j]);
                }
        }
    }

    if (MODE == 0) {
        #pragma unroll
        for (int i = 0; i < 4; i++) {
            int row = bm + wr * 64 + i * 16 + (lane >> 2);
            #pragma unroll
            for (int j = 0; j < 4; j++) {
                int col = bn + wc * 32 + j * 8 + 2 * (lane & 3);
                float b0 = bias[col], b1 = bias[col + 1];
                float2 o0; o0.x = acc[i][j][0] + b0; o0.y = acc[i][j][1] + b1;
                float2 o1; o1.x = acc[i][j][2] + b0; o1.y = acc[i][j][3] + b1;
                *(float2*)(C + (size_t)row * N + col) = o0;
                *(float2*)(C + (size_t)(row + 8) * N + col) = o1;
            }
        }
    } else {
        // fused QKV epilogue: col pairs (even, even+1) == rotary pairs
        const int sec = bn >> 10;              // 0=q, 1=k, 2=v (uniform per CTA)
        #pragma unroll
        for (int i = 0; i < 4; i++) {
            #pragma unroll
            for (int rr = 0; rr < 2; rr++) {
                int row = bm + wr * 64 + i * 16 + (lane >> 2) + rr * 8;
                int b = row >> 11, l = row & 2047;
                #pragma unroll
                for (int j = 0; j < 4; j++) {
                    int col = bn + wc * 32 + j * 8 + 2 * (lane & 3);
                    float v0 = acc[i][j][rr * 2 + 0] + bias[col];
                    float v1 = acc[i][j][rr * 2 + 1] + bias[col + 1];
                    int cs = col & 1023;
                    int h = cs >> 6, d = cs & 63, p = d >> 1;
                    size_t off = ((size_t)((b * H_ + h) * L_ + l)) * DH + d;
                    if (sec == 2) {
                        __half h0 = __float2half(v0), h1 = __float2half(v1);
                        __half2 hh; hh.x = h0; hh.y = h1;
                        __half2 ll; ll.x = __float2half(v0 - __half2float(h0));
                                    ll.y = __float2half(v1 - __half2float(h1));
                        *(__half2*)(Vh + off) = hh;
                        *(__half2*)(Vl + off) = ll;
                    } else {
                        float c = g_cos[l * 32 + p], s = g_sin[l * 32 + p];
                        float y0 = v0 * c - v1 * s;
                        float y1 = v0 * s + v1 * c;
                        if (sec == 0) {
                            y0 *= 0.125f; y1 *= 0.125f;
                            __half h0 = __float2half(y0), h1 = __float2half(y1);
                            __half2 hh; hh.x = h0; hh.y = h1;
                            __half2 ll; ll.x = __float2half(y0 - __half2float(h0));
                                        ll.y = __float2half(y1 - __half2float(h1));
                            *(__half2*)(Qh + off) = hh;
                            *(__half2*)(Ql + off) = ll;
                        } else {
                            __half2 kk; kk.x = __float2half(y0); kk.y = __float2half(y1);
                            *(__half2*)(Kh + off) = kk;
                        }
                    }
                }
            }
        }
    }
}

// ---------------- tensor-core causal flash attention, 3-stage -----------
// block: 128 q-rows (8 warps x m16), kv tiles of 64. fp16 mma, fp32 softmax.
// K/Vh/Vl smem tiles all [kv][dh]; V fragments via ldmatrix.trans.
#define AT_STRIDE 144
#define AT_KT  (64 * AT_STRIDE)       // 9216
#define AT_BUF (3 * AT_KT)            // K, Vh, Vl = 27648
#define AT_SMEM (3 * AT_BUF + 768)    // + 3 kbias slots

__global__ __launch_bounds__(256, 1) void attn_mma_kernel(
    const __half* __restrict__ Qh, const __half* __restrict__ Ql,
    const __half* __restrict__ Kh,
    const __half* __restrict__ Vh, const __half* __restrict__ Vl,
    const int* __restrict__ mask,
    __nv_bfloat16* __restrict__ Ohi, __nv_bfloat16* __restrict__ Olo)
{
    extern __shared__ char sm[];
    const uint32_t smb = smem_u32(sm);
    const int tid = threadIdx.x, lane = tid & 31, w = tid >> 5;
    const int qt = 15 - (int)blockIdx.y;        // heavy blocks first
    const int bh = blockIdx.x;
    const int b = bh >> 4, h = bh & 15;
    const int qrow0 = qt * 128 + w * 16;

    // ---- stage Q tile into smem, move to register fragments ----
    {
        const __half* s0 = Qh + ((size_t)bh * L_ + qt * 128) * DH;
        const __half* s1 = Ql + ((size_t)bh * L_ + qt * 128) * DH;
        #pragma unroll
        for (int c2 = 0; c2 < 4; c2++) {
            int idx = c2 * 256 + tid;            // 0..1023
            int row = idx >> 3, c = idx & 7;
            cp_async16(smb + row * AT_STRIDE + c * 16, s0 + (size_t)row * DH + c * 8);
            cp_async16(smb + 128 * AT_STRIDE + row * AT_STRIDE + c * 16,
                       s1 + (size_t)row * DH + c * 8);
        }
        CP_COMMIT(); CP_WAIT(0);
        __syncthreads();
    }
    uint32_t qfh[4][4], qfl[4][4];
    {
        const int lr = lane & 15, lhh = lane >> 4;
        #pragma unroll
        for (int kt = 0; kt < 4; kt++) {
            uint32_t off = (uint32_t)((w * 16 + lr) * AT_STRIDE + (kt * 2 + lhh) * 16);
            ldmx4(qfh[kt], smb + off);
            ldmx4(qfl[kt], smb + 128 * AT_STRIDE + off);
        }
    }
    __syncthreads();

    const __half* kg  = Kh + (size_t)bh * L_ * DH;
    const __half* vhg = Vh + (size_t)bh * L_ * DH;
    const __half* vlg = Vl + (size_t)bh * L_ * DH;
    const int* mp = mask + b * L_;

    auto issue = [&](int t, int buf) {
        uint32_t base = smb + buf * AT_BUF;
        int k0 = t * 64;
        #pragma unroll
        for (int hf = 0; hf < 2; hf++) {
            int idx = hf * 256 + tid;            // 0..511
            int row = idx >> 3, c = idx & 7;
            cp_async16(base + row * AT_STRIDE + c * 16,
                       kg + ((size_t)(k0 + row)) * DH + c * 8);
            cp_async16(base + AT_KT + row * AT_STRIDE + c * 16,
                       vhg + ((size_t)(k0 + row)) * DH + c * 8);
            cp_async16(base + 2 * AT_KT + row * AT_STRIDE + c * 16,
                       vlg + ((size_t)(k0 + row)) * DH + c * 8);
        }
        if (tid < 64)
            *(float*)(sm + 3 * AT_BUF + buf * 256 + tid * 4) =
                mp[k0 + tid] ? 0.f : -1e30f;
    };

    float oa[8][4];
    #pragma unroll
    for (int j = 0; j < 8; j++)
        #pragma unroll
        for (int r = 0; r < 4; r++) oa[j][r] = 0.f;
    float m0 = -1e30f, m1 = -1e30f, l0 = 0.f, l1 = 0.f;

    const int nt = (qt + 1) * 2;
    const int bjj = lane >> 4, bch = (lane >> 3) & 1, bn8 = lane & 7;
    const int t4 = (lane & 3) * 2;
    const int rg = lane >> 2;

    issue(0, 0); CP_COMMIT();
    if (nt > 1) { issue(1, 1); CP_COMMIT(); }

    for (int t = 0; t < nt; t++) {
        if (t + 1 < nt) { CP_WAIT(1); } else { CP_WAIT(0); }
        __syncthreads();
        if (t + 2 < nt) { issue(t + 2, (t + 2) % 3); CP_COMMIT(); }

        uint32_t kbase = smb + (t % 3) * AT_BUF;
        const float* kbias = (const float*)(sm + 3 * AT_BUF + (t % 3) * 256);
        int k0 = t * 64;

        // ---- S = Q K^T ----
        float sa[8][4];
        #pragma unroll
        for (int j = 0; j < 8; j++)
            #pragma unroll
            for (int r = 0; r < 4; r++) sa[j][r] = 0.f;
        #pragma unroll
        for (int jp = 0; jp < 4; jp++) {
            #pragma unroll
            for (int kt = 0; kt < 4; kt++) {
                uint32_t tmp[4];
                ldmx4(tmp, kbase + (uint32_t)(((2 * jp + bjj) * 8 + bn8) * AT_STRIDE
                                              + (kt * 2 + bch) * 16));
                mma_f16(sa[2 * jp],     qfh[kt], tmp);
                mma_f16(sa[2 * jp],     qfl[kt], tmp);
                mma_f16(sa[2 * jp + 1], qfh[kt], tmp + 2);
                mma_f16(sa[2 * jp + 1], qfl[kt], tmp + 2);
            }
        }

        // ---- key bias + causal mask ----
        #pragma unroll
        for (int j = 0; j < 8; j++) {
            float2 kb = *(const float2*)&kbias[j * 8 + t4];
            sa[j][0] += kb.x; sa[j][1] += kb.y;
            sa[j][2] += kb.x; sa[j][3] += kb.y;
        }
        if (k0 + 63 > qrow0) {
            int r0 = qrow0 + rg;
            #pragma unroll
            for (int j = 0; j < 8; j++) {
                int cc = k0 + j * 8 + t4;
                if (cc     > r0)     sa[j][0] = -1e30f;
                if (cc + 1 > r0)     sa[j][1] = -1e30f;
                if (cc     > r0 + 8) sa[j][2] = -1e30f;
                if (cc + 1 > r0 + 8) sa[j][3] = -1e30f;
            }
        }

        // ---- online softmax ----
        float mx0 = -1e30f, mx1 = -1e30f;
        #pragma unroll
        for (int j = 0; j < 8; j++) {
            mx0 = fmaxf(mx0, fmaxf(sa[j][0], sa[j][1]));
            mx1 = fmaxf(mx1, fmaxf(sa[j][2], sa[j][3]));
        }
        mx0 = fmaxf(mx0, __shfl_xor_sync(0xffffffffu, mx0, 1));
        mx0 = fmaxf(mx0, __shfl_xor_sync(0xffffffffu, mx0, 2));
        mx1 = fmaxf(mx1, __shfl_xor_sync(0xffffffffu, mx1, 1));
        mx1 = fmaxf(mx1, __shfl_xor_sync(0xffffffffu, mx1, 2));
        float mn0 = fmaxf(m0, mx0), mn1 = fmaxf(m1, mx1);
        float a0 = __expf(m0 - mn0), a1 = __expf(m1 - mn1);
        m0 = mn0; m1 = mn1;
        float s0 = 0.f, s1 = 0.f;
        #pragma unroll
        for (int j = 0; j < 8; j++) {
            sa[j][0] = __expf(sa[j][0] - mn0);
            sa[j][1] = __expf(sa[j][1] - mn0);
            sa[j][2] = __expf(sa[j][2] - mn1);
            sa[j][3] = __expf(sa[j][3] - mn1);
            s0 += sa[j][0] + sa[j][1];
            s1 += sa[j][2] + sa[j][3];
        }
        s0 += __shfl_xor_sync(0xffffffffu, s0, 1);
        s0 += __shfl_xor_sync(0xffffffffu, s0, 2);
        s1 += __shfl_xor_sync(0xffffffffu, s1, 1);
        s1 += __shfl_xor_sync(0xffffffffu, s1, 2);
        l0 = l0 * a0 + s0;
        l1 = l1 * a1 + s1;

        // ---- P fragments (fp16) ----
        uint32_t pf[4][4];
        #pragma unroll
        for (int kt = 0; kt < 4; kt++) {
            pf[kt][0] = packh2(sa[2 * kt][0],     sa[2 * kt][1]);
            pf[kt][1] = packh2(sa[2 * kt][2],     sa[2 * kt][3]);
            pf[kt][2] = packh2(sa[2 * kt + 1][0], sa[2 * kt + 1][1]);
            pf[kt][3] = packh2(sa[2 * kt + 1][2], sa[2 * kt + 1][3]);
        }

        // ---- O = O*alpha + P V  (V via ldmatrix.trans on [kv][dh] tile) --
        #pragma unroll
        for (int j = 0; j < 8; j++) {
            oa[j][0] *= a0; oa[j][1] *= a0;
            oa[j][2] *= a1; oa[j][3] *= a1;
        }
        uint32_t vhb = kbase + AT_KT, vlb = kbase + 2 * AT_KT;
        #pragma unroll
        for (int jp = 0; jp < 4; jp++) {
            #pragma unroll
            for (int kt = 0; kt < 4; kt++) {
                uint32_t off = (uint32_t)((kt * 16 + bch * 8 + bn8) * AT_STRIDE
                                          + (2 * jp + bjj) * 16);
                uint32_t tv[4];
                ldmx4t(tv, vhb + off);
                mma_f16(oa[2 * jp],     pf[kt], tv);
                mma_f16(oa[2 * jp + 1], pf[kt], tv + 2);
                ldmx4t(tv, vlb + off);
                mma_f16(oa[2 * jp],     pf[kt], tv);
                mma_f16(oa[2 * jp + 1], pf[kt], tv + 2);
            }
        }
    }

    // ---- epilogue: bf16 hi/lo split straight into proj-GEMM A buffers ----
    float i0 = 1.f / l0, i1 = 1.f / l1;
    int r0 = qrow0 + rg;
    #pragma unroll
    for (int j = 0; j < 8; j++) {
        int col = h * DH + j * 8 + t4;
        float x0 = oa[j][0] * i0, x1 = oa[j][1] * i0;
        float y0 = oa[j][2] * i1, y1 = oa[j][3] * i1;
        __nv_bfloat16 xh0 = __float2bfloat16(x0), xh1 = __float2bfloat16(x1);
        __nv_bfloat16 yh0 = __float2bfloat16(y0), yh1 = __float2bfloat16(y1);
        __nv_bfloat162 xh; xh.x = xh0; xh.y = xh1;
        __nv_bfloat162 xl; xl.x = __float2bfloat16(x0 - __bfloat162float(xh0));
                           xl.y = __float2bfloat16(x1 - __bfloat162float(xh1));
        __nv_bfloat162 yh; yh.x = yh0; yh.y = yh1;
        __nv_bfloat162 yl; yl.x = __float2bfloat16(y0 - __bfloat162float(yh0));
                           yl.y = __float2bfloat16(y1 - __bfloat162float(yh1));
        size_t ro0 = ((size_t)(b * L_ + r0)) * D_ + col;
        size_t ro1 = ((size_t)(b * L_ + r0 + 8)) * D_ + col;
        *(__nv_bfloat162*)(Ohi + ro0) = xh;
        *(__nv_bfloat162*)(Olo + ro0) = xl;
        *(__nv_bfloat162*)(Ohi + ro1) = yh;
        *(__nv_bfloat162*)(Olo + ro1) = yl;
    }
}

// ---------------- launch ------------------------------------------------
extern "C" void kernel_launch(void* const* d_in, const int* in_sizes, int n_in,
                              void* d_out, int out_size) {
    const float* x     = (const float*)d_in[0];
    const float* Wqkv  = (const float*)d_in[1];
    const float* bqkv  = (const float*)d_in[2];
    const float* Wproj = (const float*)d_in[3];
    const float* bproj = (const float*)d_in[4];
    const int*   mask  = (const int*)d_in[5];
    float* out = (float*)d_out;

    __nv_bfloat16 *ahi, *alo, *wqhi, *wqlo, *wphi, *wplo;
    __half *qh, *ql, *kh, *vh, *vl;
    cudaGetSymbolAddress((void**)&ahi,  g_ahi);
    cudaGetSymbolAddress((void**)&alo,  g_alo);
    cudaGetSymbolAddress((void**)&wqhi, g_wqhi);
    cudaGetSymbolAddress((void**)&wqlo, g_wqlo);
    cudaGetSymbolAddress((void**)&wphi, g_wphi);
    cudaGetSymbolAddress((void**)&wplo, g_wplo);
    cudaGetSymbolAddress((void**)&qh,   g_qh);
    cudaGetSymbolAddress((void**)&ql,   g_ql);
    cudaGetSymbolAddress((void**)&kh,   g_kh);
    cudaGetSymbolAddress((void**)&vh,   g_vh);
    cudaGetSymbolAddress((void**)&vl,   g_vl);

    cudaFuncSetAttribute(gemm_bf16_kernel<0>,
                         cudaFuncAttributeMaxDynamicSharedMemorySize, GEMM_SMEM);
    cudaFuncSetAttribute(gemm_bf16_kernel<1>,
                         cudaFuncAttributeMaxDynamicSharedMemorySize, GEMM_SMEM);
    cudaFuncSetAttribute(attn_mma_kernel,
                         cudaFuncAttributeMaxDynamicSharedMemorySize, AT_SMEM);

    // 1) RoPE table
    rope_table_kernel<<<(L_ * 32) / 256, 256>>>();

    // 2) operand conversions for QKV GEMM
    convert_split_kernel<<<(int)(ML * D_ / 4 / 256), 256>>>(x, ahi, alo);
    transpose_split_kernel<<<dim3(D_ / 32, 3 * D_ / 32), dim3(32, 8)>>>(
        Wqkv, wqhi, wqlo, D_, 3 * D_);
    transpose_split_kernel<<<dim3(D_ / 32, D_ / 32), dim3(32, 8)>>>(
        Wproj, wphi, wplo, D_, D_);

    // 3) QKV GEMM with fused RoPE + fp16-split epilogue
    gemm_bf16_kernel<1><<<dim3(3 * D_ / 128, (int)(ML / 128)), 256, GEMM_SMEM>>>(
        ahi, alo, wqhi, wqlo, bqkv, nullptr, 3 * D_, D_, qh, ql, kh, vh, vl);

    // 4) tensor-core causal flash attention -> bf16 hi/lo proj operands
    attn_mma_kernel<<<dim3(B_ * H_, L_ / 128), 256, AT_SMEM>>>(
        qh, ql, kh, vh, vl, mask, ahi, alo);

    // 5) output projection
    gemm_bf16_kernel<0><<<dim3(D_ / 128, (int)(ML / 128)), 256, GEMM_SMEM>>>(
        ahi, alo, wphi, wplo, bproj, out, D_, D_,
        nullptr, nullptr, nullptr, nullptr, nullptr);
}

// round 13
// speedup vs baseline: 3.9586x; 1.2860x over previous
#include <cuda_runtime.h>
#include <cuda_bf16.h>
#include <cuda_fp16.h>
#include <math.h>
#include <stdint.h>

#define B_  4
#define L_  2048
#define D_  1024
#define H_  16
#define DH  64
#define ML  ((size_t)B_ * L_)          // 8192 rows

// ---------------- scratch (no allocation allowed) ----------------
__device__ float g_cos[L_ * 32];
__device__ float g_sin[L_ * 32];
// fp16 operand buffers
__device__ __half g_ahi[ML * D_];      // A (x, then att out) hi
__device__ __half g_alo[ML * D_];      // A lo
__device__ __half g_wq[3 * D_ * D_];   // W_qkv^T fp16  [3D, D]
__device__ __half g_wp[D_ * D_];       // W_proj^T fp16 [D, D]
// fp16 attention operands (all [bh][l][64] K-major)
__device__ __half g_qh[ML * D_];       // Q hi (x0.125)
__device__ __half g_ql[ML * D_];       // Q lo
__device__ __half g_kh[ML * D_];       // K single
__device__ __half g_vh[ML * D_];       // V single

// ================= helpers =================
__device__ __forceinline__ uint32_t smem_u32(const void* p) {
    uint32_t a;
    asm("{ .reg .u64 t; cvta.to.shared.u64 t, %1; cvt.u32.u64 %0, t; }" : "=r"(a) : "l"(p));
    return a;
}
__device__ __forceinline__ void cp_async16(uint32_t smaddr, const void* gaddr) {
    asm volatile("cp.async.cg.shared.global [%0], [%1], 16;" :: "r"(smaddr), "l"(gaddr));
}
#define CP_COMMIT() asm volatile("cp.async.commit_group;" ::: "memory")
#define CP_WAIT(n)  asm volatile("cp.async.wait_group %0;" :: "n"(n) : "memory")

__device__ __forceinline__ void ldmx4(uint32_t* r, uint32_t addr) {
    asm volatile("ldmatrix.sync.aligned.m8n8.x4.shared.b16 {%0,%1,%2,%3}, [%4];"
        : "=r"(r[0]), "=r"(r[1]), "=r"(r[2]), "=r"(r[3]) : "r"(addr));
}
__device__ __forceinline__ void ldmx4t(uint32_t* r, uint32_t addr) {
    asm volatile("ldmatrix.sync.aligned.m8n8.x4.trans.shared.b16 {%0,%1,%2,%3}, [%4];"
        : "=r"(r[0]), "=r"(r[1]), "=r"(r[2]), "=r"(r[3]) : "r"(addr));
}
__device__ __forceinline__ void mma_f16(float* d, const uint32_t* a, const uint32_t* b) {
    asm volatile("mma.sync.aligned.m16n8k16.row.col.f32.f16.f16.f32 "
        "{%0,%1,%2,%3}, {%4,%5,%6,%7}, {%8,%9}, {%0,%1,%2,%3};"
        : "+f"(d[0]), "+f"(d[1]), "+f"(d[2]), "+f"(d[3])
        : "r"(a[0]), "r"(a[1]), "r"(a[2]), "r"(a[3]), "r"(b[0]), "r"(b[1]));
}
__device__ __forceinline__ uint32_t packh2(float a, float b) {
    __half2 h = __floats2half2_rn(a, b);
    return *reinterpret_cast<uint32_t*>(&h);
}

// ---------------- RoPE table (double-accurate, matches numpy f32 path) ---
__global__ void rope_table_kernel() {
    int idx = blockIdx.x * blockDim.x + threadIdx.x;   // L_*32 = 65536
    int i = idx & 31;
    int l = idx >> 5;
    double invd = exp(-(double)i * (9.210340371976184 / 32.0));
    float invf = (float)invd;
    float freq = (float)l * invf;
    g_cos[idx] = (float)cos((double)freq);
    g_sin[idx] = (float)sin((double)freq);
}

// ---------------- fp32 -> fp16 hi/lo split (elementwise) ----------------
__global__ void convert_split_kernel(const float* __restrict__ in,
    __half* __restrict__ hi, __half* __restrict__ lo)
{
    int i = blockIdx.x * blockDim.x + threadIdx.x;    // n/4 threads
    float4 v = ((const float4*)in)[i];
    __half h0 = __float2half(v.x), h1 = __float2half(v.y);
    __half h2 = __float2half(v.z), h3 = __float2half(v.w);
    __half2 hp0; hp0.x = h0; hp0.y = h1;
    __half2 hp1; hp1.x = h2; hp1.y = h3;
    __half2 lp0; lp0.x = __float2half(v.x - __half2float(h0));
                 lp0.y = __float2half(v.y - __half2float(h1));
    __half2 lp1; lp1.x = __float2half(v.z - __half2float(h2));
                 lp1.y = __float2half(v.w - __half2float(h3));
    ((__half2*)hi)[2 * i] = hp0;
    ((__half2*)hi)[2 * i + 1] = hp1;
    ((__half2*)lo)[2 * i] = lp0;
    ((__half2*)lo)[2 * i + 1] = lp1;
}

// ---------------- W [K,N] fp32 -> W^T [N,K] fp16 single -----------------
__global__ void transpose_f16_kernel(const float* __restrict__ W,
    __half* __restrict__ T, int Kd, int Nd)
{
    __shared__ float t[32][33];
    int k0 = blockIdx.x * 32, n0 = blockIdx.y * 32;
    int tx = threadIdx.x, ty = threadIdx.y;
    #pragma unroll
    for (int r = ty; r < 32; r += 8)
        t[r][tx] = W[(size_t)(k0 + r) * Nd + n0 + tx];
    __syncthreads();
    #pragma unroll
    for (int r = ty; r < 32; r += 8)
        T[(size_t)(n0 + r) * Kd + k0 + tx] = __float2half(t[tx][r]);
}

// ---------------- mma.sync fp16 GEMM: (Ahi+Alo) x B^T, 4-stage ----------
// MODE 0: C = A*B^T + bias (fp32 out).  MODE 1: fused QKV epilogue:
// rope+scale+fp16-split, writes Qh/Ql/Kh/Vh directly.
#define T_STRIDE 80
#define T_BYTES  (128 * T_STRIDE)      // 10240
#define BUF3 (3 * T_BYTES)             // Ahi, Alo, B = 30720
#define GEMM_SMEM (4 * BUF3)           // 122880

template<int MODE>
__global__ __launch_bounds__(256, 1) void gemm_f16_kernel(
    const __half* __restrict__ Ahi, const __half* __restrict__ Alo,
    const __half* __restrict__ Bm,
    const float* __restrict__ bias, float* __restrict__ C, int N, int K,
    __half* __restrict__ Qh, __half* __restrict__ Ql, __half* __restrict__ Kh,
    __half* __restrict__ Vh)
{
    extern __shared__ char smraw[];
    const uint32_t smb = smem_u32(smraw);
    const int tid = threadIdx.x;
    const int wid = tid >> 5, lane = tid & 31;
    const int wr = wid & 1, wc = wid >> 1;
    const int bn = blockIdx.x * 128, bm = blockIdx.y * 128;

    const char* gp[3];
    gp[0] = (const char*)(Ahi + (size_t)bm * K);
    gp[1] = (const char*)(Alo + (size_t)bm * K);
    gp[2] = (const char*)(Bm + (size_t)bn * K);

    const int NKB = K / 32;            // 32

    auto issue_loads = [&](int kb, int buf) {
        uint32_t sbase = smb + buf * BUF3;
        #pragma unroll
        for (int op = 0; op < 3; op++) {
            #pragma unroll
            for (int half = 0; half < 2; half++) {
                int idx = half * 256 + tid;          // 0..511
                int row = idx >> 2, c = idx & 3;
                const void* g = gp[op] + ((size_t)row * K + kb * 32 + c * 8) * 2;
                uint32_t s = sbase + op * T_BYTES + row * T_STRIDE + c * 16;
                cp_async16(s, g);
            }
        }
    };

    float acc[4][4][4];
    #pragma unroll
    for (int i = 0; i < 4; i++)
        #pragma unroll
        for (int j = 0; j < 4; j++)
            #pragma unroll
            for (int r = 0; r < 4; r++) acc[i][j][r] = 0.f;

    issue_loads(0, 0); CP_COMMIT();
    issue_loads(1, 1); CP_COMMIT();
    issue_loads(2, 2); CP_COMMIT();

    const int lr = lane & 15, lh = lane >> 4;
    const int bj = lane >> 4, bch = (lane >> 3) & 1, bn8 = lane & 7;

    for (int kb = 0; kb < NKB; kb++) {
        if (kb + 2 < NKB)      { CP_WAIT(2); }
        else if (kb + 1 < NKB) { CP_WAIT(1); }
        else                   { CP_WAIT(0); }
        __syncthreads();
        if (kb + 3 < NKB) { issue_loads(kb + 3, (kb + 3) & 3); CP_COMMIT(); }

        uint32_t sA_hi = smb + (kb & 3) * BUF3;
        uint32_t sA_lo = sA_hi + T_BYTES;
        uint32_t sB    = sA_hi + 2 * T_BYTES;

        #pragma unroll
        for (int s = 0; s < 2; s++) {
            uint32_t ahi[4][4], alo[4][4], bfr[4][2];
            #pragma unroll
            for (int i = 0; i < 4; i++) {
                uint32_t off = (uint32_t)((wr * 64 + i * 16 + lr) * T_STRIDE + (s * 2 + lh) * 16);
                ldmx4(ahi[i], sA_hi + off);
                ldmx4(alo[i], sA_lo + off);
            }
            #pragma unroll
            for (int jp = 0; jp < 2; jp++) {
                uint32_t tmp[4];
                uint32_t off = (uint32_t)((wc * 32 + (2 * jp + bj) * 8 + bn8) * T_STRIDE
                                          + (s * 2 + bch) * 16);
                ldmx4(tmp, sB + off);
                bfr[2 * jp][0] = tmp[0]; bfr[2 * jp][1] = tmp[1];
                bfr[2 * jp + 1][0] = tmp[2]; bfr[2 * jp + 1][1] = tmp[3];
            }
            #pragma unroll
            for (int i = 0; i < 4; i++)
                #pragma unroll
                for (int j = 0; j < 4; j++) {
                    mma_f16(acc[i][j], ahi[i], bfr[j]);
                    mma_f16(acc[i][j], alo[i], bfr[j]);
                }
        }
    }

    if (MODE == 0) {
        #pragma unroll
        for (int i = 0; i < 4; i++) {
            int row = bm + wr * 64 + i * 16 + (lane >> 2);
            #pragma unroll
            for (int j = 0; j < 4; j++) {
                int col = bn + wc * 32 + j * 8 + 2 * (lane & 3);
                float b0 = bias[col], b1 = bias[col + 1];
                float2 o0; o0.x = acc[i][j][0] + b0; o0.y = acc[i][j][1] + b1;
                float2 o1; o1.x = acc[i][j][2] + b0; o1.y = acc[i][j][3] + b1;
                *(float2*)(C + (size_t)row * N + col) = o0;
                *(float2*)(C + (size_t)(row + 8) * N + col) = o1;
            }
        }
    } else {
        // fused QKV epilogue: col pairs (even, even+1) == rotary pairs
        const int sec = bn >> 10;              // 0=q, 1=k, 2=v (uniform per CTA)
        #pragma unroll
        for (int i = 0; i < 4; i++) {
            #pragma unroll
            for (int rr = 0; rr < 2; rr++) {
                int row = bm + wr * 64 + i * 16 + (lane >> 2) + rr * 8;
                int b = row >> 11, l = row & 2047;
                #pragma unroll
                for (int j = 0; j < 4; j++) {
                    int col = bn + wc * 32 + j * 8 + 2 * (lane & 3);
                    float v0 = acc[i][j][rr * 2 + 0] + bias[col];
                    float v1 = acc[i][j][rr * 2 + 1] + bias[col + 1];
                    int cs = col & 1023;
                    int h = cs >> 6, d = cs & 63, p = d >> 1;
                    size_t off = ((size_t)((b * H_ + h) * L_ + l)) * DH + d;
                    if (sec == 2) {
                        __half2 hh; hh.x = __float2half(v0); hh.y = __float2half(v1);
                        *(__half2*)(Vh + off) = hh;
                    } else {
                        float c = g_cos[l * 32 + p], s = g_sin[l * 32 + p];
                        float y0 = v0 * c - v1 * s;
                        float y1 = v0 * s + v1 * c;
                        if (sec == 0) {
                            y0 *= 0.125f; y1 *= 0.125f;
                            __half h0 = __float2half(y0), h1 = __float2half(y1);
                            __half2 hh; hh.x = h0; hh.y = h1;
                            __half2 ll; ll.x = __float2half(y0 - __half2float(h0));
                                        ll.y = __float2half(y1 - __half2float(h1));
                            *(__half2*)(Qh + off) = hh;
                            *(__half2*)(Ql + off) = ll;
                        } else {
                            __half2 kk; kk.x = __float2half(y0); kk.y = __float2half(y1);
                            *(__half2*)(Kh + off) = kk;
                        }
                    }
                }
            }
        }
    }
}

// ---------------- tensor-core causal flash attention, 3-stage -----------
// block: 128 q-rows (8 warps x m16), kv tiles of 64. fp16 mma, fp32 softmax.
// K/V smem tiles [kv][dh]; V fragments via ldmatrix.trans. V single fp16.
#define AT_STRIDE 144
#define AT_KT  (64 * AT_STRIDE)       // 9216
#define AT_BUF (2 * AT_KT)            // K, V = 18432
#define AT_SMEM (3 * AT_BUF + 768)    // 56064 (>= 36864 Q staging)

__global__ __launch_bounds__(256, 1) void attn_mma_kernel(
    const __half* __restrict__ Qh, const __half* __restrict__ Ql,
    const __half* __restrict__ Kh, const __half* __restrict__ Vh,
    const int* __restrict__ mask,
    __half* __restrict__ Ohi, __half* __restrict__ Olo)
{
    extern __shared__ char sm[];
    const uint32_t smb = smem_u32(sm);
    const int tid = threadIdx.x, lane = tid & 31, w = tid >> 5;
    const int qt = 15 - (int)blockIdx.y;        // heavy blocks first
    const int bh = blockIdx.x;
    const int b = bh >> 4, h = bh & 15;
    const int qrow0 = qt * 128 + w * 16;

    // ---- stage Q tile into smem, move to register fragments ----
    {
        const __half* s0 = Qh + ((size_t)bh * L_ + qt * 128) * DH;
        const __half* s1 = Ql + ((size_t)bh * L_ + qt * 128) * DH;
        #pragma unroll
        for (int c2 = 0; c2 < 4; c2++) {
            int idx = c2 * 256 + tid;            // 0..1023
            int row = idx >> 3, c = idx & 7;
            cp_async16(smb + row * AT_STRIDE + c * 16, s0 + (size_t)row * DH + c * 8);
            cp_async16(smb + 128 * AT_STRIDE + row * AT_STRIDE + c * 16,
                       s1 + (size_t)row * DH + c * 8);
        }
        CP_COMMIT(); CP_WAIT(0);
        __syncthreads();
    }
    uint32_t qfh[4][4], qfl[4][4];
    {
        const int lr = lane & 15, lhh = lane >> 4;
        #pragma unroll
        for (int kt = 0; kt < 4; kt++) {
            uint32_t off = (uint32_t)((w * 16 + lr) * AT_STRIDE + (kt * 2 + lhh) * 16);
            ldmx4(qfh[kt], smb + off);
            ldmx4(qfl[kt], smb + 128 * AT_STRIDE + off);
        }
    }
    __syncthreads();

    const __half* kg  = Kh + (size_t)bh * L_ * DH;
    const __half* vhg = Vh + (size_t)bh * L_ * DH;
    const int* mp = mask + b * L_;

    auto issue = [&](int t, int buf) {
        uint32_t base = smb + buf * AT_BUF;
        int k0 = t * 64;
        #pragma unroll
        for (int hf = 0; hf < 2; hf++) {
            int idx = hf * 256 + tid;            // 0..511
            int row = idx >> 3, c = idx & 7;
            cp_async16(base + row * AT_STRIDE + c * 16,
                       kg + ((size_t)(k0 + row)) * DH + c * 8);
            cp_async16(base + AT_KT + row * AT_STRIDE + c * 16,
                       vhg + ((size_t)(k0 + row)) * DH + c * 8);
        }
        if (tid < 64)
            *(float*)(sm + 3 * AT_BUF + buf * 256 + tid * 4) =
                mp[k0 + tid] ? 0.f : -1e30f;
    };

    float oa[8][4];
    #pragma unroll
    for (int j = 0; j < 8; j++)
        #pragma unroll
        for (int r = 0; r < 4; r++) oa[j][r] = 0.f;
    float m0 = -1e30f, m1 = -1e30f, l0 = 0.f, l1 = 0.f;

    const int nt = (qt + 1) * 2;
    const int bjj = lane >> 4, bch = (lane >> 3) & 1, bn8 = lane & 7;
    const int t4 = (lane & 3) * 2;
    const int rg = lane >> 2;

    issue(0, 0); CP_COMMIT();
    if (nt > 1) { issue(1, 1); CP_COMMIT(); }

    for (int t = 0; t < nt; t++) {
        if (t + 1 < nt) { CP_WAIT(1); } else { CP_WAIT(0); }
        __syncthreads();
        if (t + 2 < nt) { issue(t + 2, (t + 2) % 3); CP_COMMIT(); }

        uint32_t kbase = smb + (t % 3) * AT_BUF;
        const float* kbias = (const float*)(sm + 3 * AT_BUF + (t % 3) * 256);
        int k0 = t * 64;

        // ---- S = Q K^T ----
        float sa[8][4];
        #pragma unroll
        for (int j = 0; j < 8; j++)
            #pragma unroll
            for (int r = 0; r < 4; r++) sa[j][r] = 0.f;
        #pragma unroll
        for (int jp = 0; jp < 4; jp++) {
            #pragma unroll
            for (int kt = 0; kt < 4; kt++) {
                uint32_t tmp[4];
                ldmx4(tmp, kbase + (uint32_t)(((2 * jp + bjj) * 8 + bn8) * AT_STRIDE
                                              + (kt * 2 + bch) * 16));
                mma_f16(sa[2 * jp],     qfh[kt], tmp);
                mma_f16(sa[2 * jp],     qfl[kt], tmp);
                mma_f16(sa[2 * jp + 1], qfh[kt], tmp + 2);
                mma_f16(sa[2 * jp + 1], qfl[kt], tmp + 2);
            }
        }

        // ---- key bias + causal mask ----
        #pragma unroll
        for (int j = 0; j < 8; j++) {
            float2 kb = *(const float2*)&kbias[j * 8 + t4];
            sa[j][0] += kb.x; sa[j][1] += kb.y;
            sa[j][2] += kb.x; sa[j][3] += kb.y;
        }
        if (k0 + 63 > qrow0) {
            int r0 = qrow0 + rg;
            #pragma unroll
            for (int j = 0; j < 8; j++) {
                int cc = k0 + j * 8 + t4;
                if (cc     > r0)     sa[j][0] = -1e30f;
                if (cc + 1 > r0)     sa[j][1] = -1e30f;
                if (cc     > r0 + 8) sa[j][2] = -1e30f;
                if (cc + 1 > r0 + 8) sa[j][3] = -1e30f;
            }
        }

        // ---- online softmax ----
        float mx0 = -1e30f, mx1 = -1e30f;
        #pragma unroll
        for (int j = 0; j < 8; j++) {
            mx0 = fmaxf(mx0, fmaxf(sa[j][0], sa[j][1]));
            mx1 = fmaxf(mx1, fmaxf(sa[j][2], sa[j][3]));
        }
        mx0 = fmaxf(mx0, __shfl_xor_sync(0xffffffffu, mx0, 1));
        mx0 = fmaxf(mx0, __shfl_xor_sync(0xffffffffu, mx0, 2));
        mx1 = fmaxf(mx1, __shfl_xor_sync(0xffffffffu, mx1, 1));
        mx1 = fmaxf(mx1, __shfl_xor_sync(0xffffffffu, mx1, 2));
        float mn0 = fmaxf(m0, mx0), mn1 = fmaxf(m1, mx1);
        float a0 = __expf(m0 - mn0), a1 = __expf(m1 - mn1);
        m0 = mn0; m1 = mn1;
        float s0 = 0.f, s1 = 0.f;
        #pragma unroll
        for (int j = 0; j < 8; j++) {
            sa[j][0] = __expf(sa[j][0] - mn0);
            sa[j][1] = __expf(sa[j][1] - mn0);
            sa[j][2] = __expf(sa[j][2] - mn1);
            sa[j][3] = __expf(sa[j][3] - mn1);
            s0 += sa[j][0] + sa[j][1];
            s1 += sa[j][2] + sa[j][3];
        }
        s0 += __shfl_xor_sync(0xffffffffu, s0, 1);
        s0 += __shfl_xor_sync(0xffffffffu, s0, 2);
        s1 += __shfl_xor_sync(0xffffffffu, s1, 1);
        s1 += __shfl_xor_sync(0xffffffffu, s1, 2);
        l0 = l0 * a0 + s0;
        l1 = l1 * a1 + s1;

        // ---- P fragments (fp16) ----
        uint32_t pf[4][4];
        #pragma unroll
        for (int kt = 0; kt < 4; kt++) {
            pf[kt][0] = packh2(sa[2 * kt][0],     sa[2 * kt][1]);
            pf[kt][1] = packh2(sa[2 * kt][2],     sa[2 * kt][3]);
            pf[kt][2] = packh2(sa[2 * kt + 1][0], sa[2 * kt + 1][1]);
            pf[kt][3] = packh2(sa[2 * kt + 1][2], sa[2 * kt + 1][3]);
        }

        // ---- O = O*alpha + P V  (V via ldmatrix.trans on [kv][dh] tile) --
        #pragma unroll
        for (int j = 0; j < 8; j++) {
            oa[j][0] *= a0; oa[j][1] *= a0;
            oa[j][2] *= a1; oa[j][3] *= a1;
        }
        uint32_t vhb = kbase + AT_KT;
        #pragma unroll
        for (int jp = 0; jp < 4; jp++) {
            #pragma unroll
            for (int kt = 0; kt < 4; kt++) {
                uint32_t off = (uint32_t)((kt * 16 + bch * 8 + bn8) * AT_STRIDE
                                          + (2 * jp + bjj) * 16);
                uint32_t tv[4];
                ldmx4t(tv, vhb + off);
                mma_f16(oa[2 * jp],     pf[kt], tv);
                mma_f16(oa[2 * jp + 1], pf[kt], tv + 2);
            }
        }
    }

    // ---- epilogue: fp16 hi/lo split straight into proj-GEMM A buffers ----
    float i0 = 1.f / l0, i1 = 1.f / l1;
    int r0 = qrow0 + rg;
    #pragma unroll
    for (int j = 0; j < 8; j++) {
        int col = h * DH + j * 8 + t4;
        float x0 = oa[j][0] * i0, x1 = oa[j][1] * i0;
        float y0 = oa[j][2] * i1, y1 = oa[j][3] * i1;
        __half xh0 = __float2half(x0), xh1 = __float2half(x1);
        __half yh0 = __float2half(y0), yh1 = __float2half(y1);
        __half2 xh; xh.x = xh0; xh.y = xh1;
        __half2 xl; xl.x = __float2half(x0 - __half2float(xh0));
                    xl.y = __float2half(x1 - __half2float(xh1));
        __half2 yh; yh.x = yh0; yh.y = yh1;
        __half2 yl; yl.x = __float2half(y0 - __half2float(yh0));
                    yl.y = __float2half(y1 - __half2float(yh1));
        size_t ro0 = ((size_t)(b * L_ + r0)) * D_ + col;
        size_t ro1 = ((size_t)(b * L_ + r0 + 8)) * D_ + col;
        *(__half2*)(Ohi + ro0) = xh;
        *(__half2*)(Olo + ro0) = xl;
        *(__half2*)(Ohi + ro1) = yh;
        *(__half2*)(Olo + ro1) = yl;
    }
}

// ---------------- launch ------------------------------------------------
extern "C" void kernel_launch(void* const* d_in, const int* in_sizes, int n_in,
                              void* d_out, int out_size) {
    const float* x     = (const float*)d_in[0];
    const float* Wqkv  = (const float*)d_in[1];
    const float* bqkv  = (const float*)d_in[2];
    const float* Wproj = (const float*)d_in[3];
    const float* bproj = (const float*)d_in[4];
    const int*   mask  = (const int*)d_in[5];
    float* out = (float*)d_out;

    __half *ahi, *alo, *wq, *wp, *qh, *ql, *kh, *vh;
    cudaGetSymbolAddress((void**)&ahi, g_ahi);
    cudaGetSymbolAddress((void**)&alo, g_alo);
    cudaGetSymbolAddress((void**)&wq,  g_wq);
    cudaGetSymbolAddress((void**)&wp,  g_wp);
    cudaGetSymbolAddress((void**)&qh,  g_qh);
    cudaGetSymbolAddress((void**)&ql,  g_ql);
    cudaGetSymbolAddress((void**)&kh,  g_kh);
    cudaGetSymbolAddress((void**)&vh,  g_vh);

    cudaFuncSetAttribute(gemm_f16_kernel<0>,
                         cudaFuncAttributeMaxDynamicSharedMemorySize, GEMM_SMEM);
    cudaFuncSetAttribute(gemm_f16_kernel<1>,
                         cudaFuncAttributeMaxDynamicSharedMemorySize, GEMM_SMEM);
    cudaFuncSetAttribute(attn_mma_kernel,
                         cudaFuncAttributeMaxDynamicSharedMemorySize, AT_SMEM);

    // 1) RoPE table
    rope_table_kernel<<<(L_ * 32) / 256, 256>>>();

    // 2) operand conversions
    convert_split_kernel<<<(int)(ML * D_ / 4 / 256), 256>>>(x, ahi, alo);
    transpose_f16_kernel<<<dim3(D_ / 32, 3 * D_ / 32), dim3(32, 8)>>>(
        Wqkv, wq, D_, 3 * D_);
    transpose_f16_kernel<<<dim3(D_ / 32, D_ / 32), dim3(32, 8)>>>(
        Wproj, wp, D_, D_);

    // 3) QKV GEMM with fused RoPE + fp16-split epilogue
    gemm_f16_kernel<1><<<dim3(3 * D_ / 128, (int)(ML / 128)), 256, GEMM_SMEM>>>(
        ahi, alo, wq, bqkv, nullptr, 3 * D_, D_, qh, ql, kh, vh);

    // 4) tensor-core causal flash attention -> fp16 hi/lo proj operands
    attn_mma_kernel<<<dim3(B_ * H_, L_ / 128), 256, AT_SMEM>>>(
        qh, ql, kh, vh, mask, ahi, alo);

    // 5) output projection
    gemm_f16_kernel<0><<<dim3(D_ / 128, (int)(ML / 128)), 256, GEMM_SMEM>>>(
        ahi, alo, wp, bproj, out, D_, D_,
        nullptr, nullptr, nullptr, nullptr);
}

// round 15
// speedup vs baseline: 6.1278x; 1.5480x over previous
#include <cuda_runtime.h>
#include <cuda_bf16.h>
#include <cuda_fp16.h>
#include <math.h>
#include <stdint.h>

#define B_  4
#define L_  2048
#define D_  1024
#define H_  16
#define DH  64
#define ML  ((size_t)B_ * L_)          // 8192 rows

// ---------------- scratch (no allocation allowed) ----------------
__device__ float g_cos[L_ * 32];
__device__ float g_sin[L_ * 32];
// fp16 operand buffers
__device__ __half g_a[ML * D_];        // A (x, then att out) single fp16
__device__ __half g_wq[3 * D_ * D_];   // W_qkv^T fp16  [3D, D]
__device__ __half g_wp[D_ * D_];       // W_proj^T fp16 [D, D]
// fp16 attention operands (all [bh][l][64] K-major)
__device__ __half g_qh[ML * D_];       // Q hi (x0.125)
__device__ __half g_ql[ML * D_];       // Q lo
__device__ __half g_kh[ML * D_];       // K single
__device__ __half g_vh[ML * D_];       // V single

// ================= helpers =================
__device__ __forceinline__ uint32_t smem_u32(const void* p) {
    uint32_t a;
    asm("{ .reg .u64 t; cvta.to.shared.u64 t, %1; cvt.u32.u64 %0, t; }" : "=r"(a) : "l"(p));
    return a;
}
__device__ __forceinline__ void cp_async16(uint32_t smaddr, const void* gaddr) {
    asm volatile("cp.async.cg.shared.global [%0], [%1], 16;" :: "r"(smaddr), "l"(gaddr));
}
#define CP_COMMIT() asm volatile("cp.async.commit_group;" ::: "memory")
#define CP_WAIT(n)  asm volatile("cp.async.wait_group %0;" :: "n"(n) : "memory")

__device__ __forceinline__ void ldmx4(uint32_t* r, uint32_t addr) {
    asm volatile("ldmatrix.sync.aligned.m8n8.x4.shared.b16 {%0,%1,%2,%3}, [%4];"
        : "=r"(r[0]), "=r"(r[1]), "=r"(r[2]), "=r"(r[3]) : "r"(addr));
}
__device__ __forceinline__ void ldmx4t(uint32_t* r, uint32_t addr) {
    asm volatile("ldmatrix.sync.aligned.m8n8.x4.trans.shared.b16 {%0,%1,%2,%3}, [%4];"
        : "=r"(r[0]), "=r"(r[1]), "=r"(r[2]), "=r"(r[3]) : "r"(addr));
}
__device__ __forceinline__ void mma_f16(float* d, const uint32_t* a, const uint32_t* b) {
    asm volatile("mma.sync.aligned.m16n8k16.row.col.f32.f16.f16.f32 "
        "{%0,%1,%2,%3}, {%4,%5,%6,%7}, {%8,%9}, {%0,%1,%2,%3};"
        : "+f"(d[0]), "+f"(d[1]), "+f"(d[2]), "+f"(d[3])
        : "r"(a[0]), "r"(a[1]), "r"(a[2]), "r"(a[3]), "r"(b[0]), "r"(b[1]));
}
__device__ __forceinline__ uint32_t packh2(float a, float b) {
    __half2 h = __floats2half2_rn(a, b);
    return *reinterpret_cast<uint32_t*>(&h);
}

// ---------------- RoPE table (double-accurate, matches numpy f32 path) ---
__global__ void rope_table_kernel() {
    int idx = blockIdx.x * blockDim.x + threadIdx.x;   // L_*32 = 65536
    int i = idx & 31;
    int l = idx >> 5;
    double invd = exp(-(double)i * (9.210340371976184 / 32.0));
    float invf = (float)invd;
    float freq = (float)l * invf;
    g_cos[idx] = (float)cos((double)freq);
    g_sin[idx] = (float)sin((double)freq);
}

// ---------------- fp32 -> fp16 (elementwise) ----------------------------
__global__ void convert_f16_kernel(const float* __restrict__ in,
    __half* __restrict__ out)
{
    int i = blockIdx.x * blockDim.x + threadIdx.x;    // n/4 threads
    float4 v = ((const float4*)in)[i];
    __half2 p0; p0.x = __float2half(v.x); p0.y = __float2half(v.y);
    __half2 p1; p1.x = __float2half(v.z); p1.y = __float2half(v.w);
    ((__half2*)out)[2 * i] = p0;
    ((__half2*)out)[2 * i + 1] = p1;
}

// ---------------- W [K,N] fp32 -> W^T [N,K] fp16 single -----------------
__global__ void transpose_f16_kernel(const float* __restrict__ W,
    __half* __restrict__ T, int Kd, int Nd)
{
    __shared__ float t[32][33];
    int k0 = blockIdx.x * 32, n0 = blockIdx.y * 32;
    int tx = threadIdx.x, ty = threadIdx.y;
    #pragma unroll
    for (int r = ty; r < 32; r += 8)
        t[r][tx] = W[(size_t)(k0 + r) * Nd + n0 + tx];
    __syncthreads();
    #pragma unroll
    for (int r = ty; r < 32; r += 8)
        T[(size_t)(n0 + r) * Kd + k0 + tx] = __float2half(t[tx][r]);
}

// ---------------- mma.sync fp16 GEMM: A x B^T, 4-stage, occ 2 -----------
// MODE 0: C = A*B^T + bias (fp32 out).  MODE 1: fused QKV epilogue:
// rope+scale+fp16-split, writes Qh/Ql/Kh/Vh directly.
#define T_STRIDE 80
#define T_BYTES  (128 * T_STRIDE)      // 10240
#define BUF2 (2 * T_BYTES)             // A, B = 20480
#define GEMM_SMEM (4 * BUF2)           // 81920

template<int MODE>
__global__ __launch_bounds__(256, 2) void gemm_f16_kernel(
    const __half* __restrict__ Am, const __half* __restrict__ Bm,
    const float* __restrict__ bias, float* __restrict__ C, int N, int K,
    __half* __restrict__ Qh, __half* __restrict__ Ql, __half* __restrict__ Kh,
    __half* __restrict__ Vh)
{
    extern __shared__ char smraw[];
    const uint32_t smb = smem_u32(smraw);
    const int tid = threadIdx.x;
    const int wid = tid >> 5, lane = tid & 31;
    const int wr = wid & 1, wc = wid >> 1;
    const int bn = blockIdx.x * 128, bm = blockIdx.y * 128;

    const char* gp[2];
    gp[0] = (const char*)(Am + (size_t)bm * K);
    gp[1] = (const char*)(Bm + (size_t)bn * K);

    const int NKB = K / 32;            // 32

    auto issue_loads = [&](int kb, int buf) {
        uint32_t sbase = smb + buf * BUF2;
        #pragma unroll
        for (int op = 0; op < 2; op++) {
            #pragma unroll
            for (int half = 0; half < 2; half++) {
                int idx = half * 256 + tid;          // 0..511
                int row = idx >> 2, c = idx & 3;
                const void* g = gp[op] + ((size_t)row * K + kb * 32 + c * 8) * 2;
                uint32_t s = sbase + op * T_BYTES + row * T_STRIDE + c * 16;
                cp_async16(s, g);
            }
        }
    };

    float acc[4][4][4];
    #pragma unroll
    for (int i = 0; i < 4; i++)
        #pragma unroll
        for (int j = 0; j < 4; j++)
            #pragma unroll
            for (int r = 0; r < 4; r++) acc[i][j][r] = 0.f;

    issue_loads(0, 0); CP_COMMIT();
    issue_loads(1, 1); CP_COMMIT();
    issue_loads(2, 2); CP_COMMIT();

    const int lr = lane & 15, lh = lane >> 4;
    const int bj = lane >> 4, bch = (lane >> 3) & 1, bn8 = lane & 7;

    for (int kb = 0; kb < NKB; kb++) {
        if (kb + 2 < NKB)      { CP_WAIT(2); }
        else if (kb + 1 < NKB) { CP_WAIT(1); }
        else                   { CP_WAIT(0); }
        __syncthreads();
        if (kb + 3 < NKB) { issue_loads(kb + 3, (kb + 3) & 3); CP_COMMIT(); }

        uint32_t sA = smb + (kb & 3) * BUF2;
        uint32_t sB = sA + T_BYTES;

        #pragma unroll
        for (int s = 0; s < 2; s++) {
            uint32_t afr[4][4], bfr[4][2];
            #pragma unroll
            for (int i = 0; i < 4; i++) {
                uint32_t off = (uint32_t)((wr * 64 + i * 16 + lr) * T_STRIDE + (s * 2 + lh) * 16);
                ldmx4(afr[i], sA + off);
            }
            #pragma unroll
            for (int jp = 0; jp < 2; jp++) {
                uint32_t tmp[4];
                uint32_t off = (uint32_t)((wc * 32 + (2 * jp + bj) * 8 + bn8) * T_STRIDE
                                          + (s * 2 + bch) * 16);
                ldmx4(tmp, sB + off);
                bfr[2 * jp][0] = tmp[0]; bfr[2 * jp][1] = tmp[1];
                bfr[2 * jp + 1][0] = tmp[2]; bfr[2 * jp + 1][1] = tmp[3];
            }
            #pragma unroll
            for (int i = 0; i < 4; i++)
                #pragma unroll
                for (int j = 0; j < 4; j++)
                    mma_f16(acc[i][j], afr[i], bfr[j]);
        }
    }

    if (MODE == 0) {
        #pragma unroll
        for (int i = 0; i < 4; i++) {
            int row = bm + wr * 64 + i * 16 + (lane >> 2);
            #pragma unroll
            for (int j = 0; j < 4; j++) {
                int col = bn + wc * 32 + j * 8 + 2 * (lane & 3);
                float b0 = bias[col], b1 = bias[col + 1];
                float2 o0; o0.x = acc[i][j][0] + b0; o0.y = acc[i][j][1] + b1;
                float2 o1; o1.x = acc[i][j][2] + b0; o1.y = acc[i][j][3] + b1;
                *(float2*)(C + (size_t)row * N + col) = o0;
                *(float2*)(C + (size_t)(row + 8) * N + col) = o1;
            }
        }
    } else {
        // fused QKV epilogue: col pairs (even, even+1) == rotary pairs
        const int sec = bn >> 10;              // 0=q, 1=k, 2=v (uniform per CTA)
        #pragma unroll
        for (int i = 0; i < 4; i++) {
            #pragma unroll
            for (int rr = 0; rr < 2; rr++) {
                int row = bm + wr * 64 + i * 16 + (lane >> 2) + rr * 8;
                int b = row >> 11, l = row & 2047;
                #pragma unroll
                for (int j = 0; j < 4; j++) {
                    int col = bn + wc * 32 + j * 8 + 2 * (lane & 3);
                    float v0 = acc[i][j][rr * 2 + 0] + bias[col];
                    float v1 = acc[i][j][rr * 2 + 1] + bias[col + 1];
                    int cs = col & 1023;
                    int h = cs >> 6, d = cs & 63, p = d >> 1;
                    size_t off = ((size_t)((b * H_ + h) * L_ + l)) * DH + d;
                    if (sec == 2) {
                        __half2 hh; hh.x = __float2half(v0); hh.y = __float2half(v1);
                        *(__half2*)(Vh + off) = hh;
                    } else {
                        float c = g_cos[l * 32 + p], s = g_sin[l * 32 + p];
                        float y0 = v0 * c - v1 * s;
                        float y1 = v0 * s + v1 * c;
                        if (sec == 0) {
                            y0 *= 0.125f; y1 *= 0.125f;
                            __half h0 = __float2half(y0), h1 = __float2half(y1);
                            __half2 hh; hh.x = h0; hh.y = h1;
                            __half2 ll; ll.x = __float2half(y0 - __half2float(h0));
                                        ll.y = __float2half(y1 - __half2float(h1));
                            *(__half2*)(Qh + off) = hh;
                            *(__half2*)(Ql + off) = ll;
                        } else {
                            __half2 kk; kk.x = __float2half(y0); kk.y = __float2half(y1);
                            *(__half2*)(Kh + off) = kk;
                        }
                    }
                }
            }
        }
    }
}

// ---------------- tensor-core causal flash attention, 3-stage -----------
// block: 128 q-rows (8 warps x m16), kv tiles of 64. fp16 mma, fp32 softmax.
// K/V smem tiles [kv][dh]; V fragments via ldmatrix.trans. V single fp16.
#define AT_STRIDE 144
#define AT_KT  (64 * AT_STRIDE)       // 9216
#define AT_BUF (2 * AT_KT)            // K, V = 18432
#define AT_SMEM (3 * AT_BUF + 768)    // 56064 (>= 36864 Q staging)

__global__ __launch_bounds__(256, 1) void attn_mma_kernel(
    const __half* __restrict__ Qh, const __half* __restrict__ Ql,
    const __half* __restrict__ Kh, const __half* __restrict__ Vh,
    const int* __restrict__ mask,
    __half* __restrict__ Oout)
{
    extern __shared__ char sm[];
    const uint32_t smb = smem_u32(sm);
    const int tid = threadIdx.x, lane = tid & 31, w = tid >> 5;
    const int qt = 15 - (int)blockIdx.y;        // heavy blocks first
    const int bh = blockIdx.x;
    const int b = bh >> 4, h = bh & 15;
    const int qrow0 = qt * 128 + w * 16;

    // ---- stage Q tile into smem, move to register fragments ----
    {
        const __half* s0 = Qh + ((size_t)bh * L_ + qt * 128) * DH;
        const __half* s1 = Ql + ((size_t)bh * L_ + qt * 128) * DH;
        #pragma unroll
        for (int c2 = 0; c2 < 4; c2++) {
            int idx = c2 * 256 + tid;            // 0..1023
            int row = idx >> 3, c = idx & 7;
            cp_async16(smb + row * AT_STRIDE + c * 16, s0 + (size_t)row * DH + c * 8);
            cp_async16(smb + 128 * AT_STRIDE + row * AT_STRIDE + c * 16,
                       s1 + (size_t)row * DH + c * 8);
        }
        CP_COMMIT(); CP_WAIT(0);
        __syncthreads();
    }
    uint32_t qfh[4][4], qfl[4][4];
    {
        const int lr = lane & 15, lhh = lane >> 4;
        #pragma unroll
        for (int kt = 0; kt < 4; kt++) {
            uint32_t off = (uint32_t)((w * 16 + lr) * AT_STRIDE + (kt * 2 + lhh) * 16);
            ldmx4(qfh[kt], smb + off);
            ldmx4(qfl[kt], smb + 128 * AT_STRIDE + off);
        }
    }
    __syncthreads();

    const __half* kg  = Kh + (size_t)bh * L_ * DH;
    const __half* vhg = Vh + (size_t)bh * L_ * DH;
    const int* mp = mask + b * L_;

    auto issue = [&](int t, int buf) {
        uint32_t base = smb + buf * AT_BUF;
        int k0 = t * 64;
        #pragma unroll
        for (int hf = 0; hf < 2; hf++) {
            int idx = hf * 256 + tid;            // 0..511
            int row = idx >> 3, c = idx & 7;
            cp_async16(base + row * AT_STRIDE + c * 16,
                       kg + ((size_t)(k0 + row)) * DH + c * 8);
            cp_async16(base + AT_KT + row * AT_STRIDE + c * 16,
                       vhg + ((size_t)(k0 + row)) * DH + c * 8);
        }
        if (tid < 64)
            *(float*)(sm + 3 * AT_BUF + buf * 256 + tid * 4) =
                mp[k0 + tid] ? 0.f : -1e30f;
    };

    float oa[8][4];
    #pragma unroll
    for (int j = 0; j < 8; j++)
        #pragma unroll
        for (int r = 0; r < 4; r++) oa[j][r] = 0.f;
    float m0 = -1e30f, m1 = -1e30f, l0 = 0.f, l1 = 0.f;

    const int nt = (qt + 1) * 2;
    const int bjj = lane >> 4, bch = (lane >> 3) & 1, bn8 = lane & 7;
    const int t4 = (lane & 3) * 2;
    const int rg = lane >> 2;

    issue(0, 0); CP_COMMIT();
    if (nt > 1) { issue(1, 1); CP_COMMIT(); }

    for (int t = 0; t < nt; t++) {
        if (t + 1 < nt) { CP_WAIT(1); } else { CP_WAIT(0); }
        __syncthreads();
        if (t + 2 < nt) { issue(t + 2, (t + 2) % 3); CP_COMMIT(); }

        uint32_t kbase = smb + (t % 3) * AT_BUF;
        const float* kbias = (const float*)(sm + 3 * AT_BUF + (t % 3) * 256);
        int k0 = t * 64;

        // ---- S = Q K^T ----
        float sa[8][4];
        #pragma unroll
        for (int j = 0; j < 8; j++)
            #pragma unroll
            for (int r = 0; r < 4; r++) sa[j][r] = 0.f;
        #pragma unroll
        for (int jp = 0; jp < 4; jp++) {
            #pragma unroll
            for (int kt = 0; kt < 4; kt++) {
                uint32_t tmp[4];
                ldmx4(tmp, kbase + (uint32_t)(((2 * jp + bjj) * 8 + bn8) * AT_STRIDE
                                              + (kt * 2 + bch) * 16));
                mma_f16(sa[2 * jp],     qfh[kt], tmp);
                mma_f16(sa[2 * jp],     qfl[kt], tmp);
                mma_f16(sa[2 * jp + 1], qfh[kt], tmp + 2);
                mma_f16(sa[2 * jp + 1], qfl[kt], tmp + 2);
            }
        }

        // ---- key bias + causal mask ----
        #pragma unroll
        for (int j = 0; j < 8; j++) {
            float2 kb = *(const float2*)&kbias[j * 8 + t4];
            sa[j][0] += kb.x; sa[j][1] += kb.y;
            sa[j][2] += kb.x; sa[j][3] += kb.y;
        }
        if (k0 + 63 > qrow0) {
            int r0 = qrow0 + rg;
            #pragma unroll
            for (int j = 0; j < 8; j++) {
                int cc = k0 + j * 8 + t4;
                if (cc     > r0)     sa[j][0] = -1e30f;
                if (cc + 1 > r0)     sa[j][1] = -1e30f;
                if (cc     > r0 + 8) sa[j][2] = -1e30f;
                if (cc + 1 > r0 + 8) sa[j][3] = -1e30f;
            }
        }

        // ---- online softmax ----
        float mx0 = -1e30f, mx1 = -1e30f;
        #pragma unroll
        for (int j = 0; j < 8; j++) {
            mx0 = fmaxf(mx0, fmaxf(sa[j][0], sa[j][1]));
            mx1 = fmaxf(mx1, fmaxf(sa[j][2], sa[j][3]));
        }
        mx0 = fmaxf(mx0, __shfl_xor_sync(0xffffffffu, mx0, 1));
        mx0 = fmaxf(mx0, __shfl_xor_sync(0xffffffffu, mx0, 2));
        mx1 = fmaxf(mx1, __shfl_xor_sync(0xffffffffu, mx1, 1));
        mx1 = fmaxf(mx1, __shfl_xor_sync(0xffffffffu, mx1, 2));
        float mn0 = fmaxf(m0, mx0), mn1 = fmaxf(m1, mx1);
        float a0 = __expf(m0 - mn0), a1 = __expf(m1 - mn1);
        m0 = mn0; m1 = mn1;
        float s0 = 0.f, s1 = 0.f;
        #pragma unroll
        for (int j = 0; j < 8; j++) {
            sa[j][0] = __expf(sa[j][0] - mn0);
            sa[j][1] = __expf(sa[j][1] - mn0);
            sa[j][2] = __expf(sa[j][2] - mn1);
            sa[j][3] = __expf(sa[j][3] - mn1);
            s0 += sa[j][0] + sa[j][1];
            s1 += sa[j][2] + sa[j][3];
        }
        s0 += __shfl_xor_sync(0xffffffffu, s0, 1);
        s0 += __shfl_xor_sync(0xffffffffu, s0, 2);
        s1 += __shfl_xor_sync(0xffffffffu, s1, 1);
        s1 += __shfl_xor_sync(0xffffffffu, s1, 2);
        l0 = l0 * a0 + s0;
        l1 = l1 * a1 + s1;

        // ---- P fragments (fp16) ----
        uint32_t pf[4][4];
        #pragma unroll
        for (int kt = 0; kt < 4; kt++) {
            pf[kt][0] = packh2(sa[2 * kt][0],     sa[2 * kt][1]);
            pf[kt][1] = packh2(sa[2 * kt][2],     sa[2 * kt][3]);
            pf[kt][2] = packh2(sa[2 * kt + 1][0], sa[2 * kt + 1][1]);
            pf[kt][3] = packh2(sa[2 * kt + 1][2], sa[2 * kt + 1][3]);
        }

        // ---- O = O*alpha + P V  (V via ldmatrix.trans on [kv][dh] tile) --
        #pragma unroll
        for (int j = 0; j < 8; j++) {
            oa[j][0] *= a0; oa[j][1] *= a0;
            oa[j][2] *= a1; oa[j][3] *= a1;
        }
        uint32_t vhb = kbase + AT_KT;
        #pragma unroll
        for (int jp = 0; jp < 4; jp++) {
            #pragma unroll
            for (int kt = 0; kt < 4; kt++) {
                uint32_t off = (uint32_t)((kt * 16 + bch * 8 + bn8) * AT_STRIDE
                                          + (2 * jp + bjj) * 16);
                uint32_t tv[4];
                ldmx4t(tv, vhb + off);
                mma_f16(oa[2 * jp],     pf[kt], tv);
                mma_f16(oa[2 * jp + 1], pf[kt], tv + 2);
            }
        }
    }

    // ---- epilogue: fp16 straight into proj-GEMM A buffer ----
    float i0 = 1.f / l0, i1 = 1.f / l1;
    int r0 = qrow0 + rg;
    #pragma unroll
    for (int j = 0; j < 8; j++) {
        int col = h * DH + j * 8 + t4;
        float x0 = oa[j][0] * i0, x1 = oa[j][1] * i0;
        float y0 = oa[j][2] * i1, y1 = oa[j][3] * i1;
        __half2 xh; xh.x = __float2half(x0); xh.y = __float2half(x1);
        __half2 yh; yh.x = __float2half(y0); yh.y = __float2half(y1);
        size_t ro0 = ((size_t)(b * L_ + r0)) * D_ + col;
        size_t ro1 = ((size_t)(b * L_ + r0 + 8)) * D_ + col;
        *(__half2*)(Oout + ro0) = xh;
        *(__half2*)(Oout + ro1) = yh;
    }
}

// ---------------- launch ------------------------------------------------
extern "C" void kernel_launch(void* const* d_in, const int* in_sizes, int n_in,
                              void* d_out, int out_size) {
    const float* x     = (const float*)d_in[0];
    const float* Wqkv  = (const float*)d_in[1];
    const float* bqkv  = (const float*)d_in[2];
    const float* Wproj = (const float*)d_in[3];
    const float* bproj = (const float*)d_in[4];
    const int*   mask  = (const int*)d_in[5];
    float* out = (float*)d_out;

    __half *a, *wq, *wp, *qh, *ql, *kh, *vh;
    cudaGetSymbolAddress((void**)&a,  g_a);
    cudaGetSymbolAddress((void**)&wq, g_wq);
    cudaGetSymbolAddress((void**)&wp, g_wp);
    cudaGetSymbolAddress((void**)&qh, g_qh);
    cudaGetSymbolAddress((void**)&ql, g_ql);
    cudaGetSymbolAddress((void**)&kh, g_kh);
    cudaGetSymbolAddress((void**)&vh, g_vh);

    cudaFuncSetAttribute(gemm_f16_kernel<0>,
                         cudaFuncAttributeMaxDynamicSharedMemorySize, GEMM_SMEM);
    cudaFuncSetAttribute(gemm_f16_kernel<1>,
                         cudaFuncAttributeMaxDynamicSharedMemorySize, GEMM_SMEM);
    cudaFuncSetAttribute(attn_mma_kernel,
                         cudaFuncAttributeMaxDynamicSharedMemorySize, AT_SMEM);

    // 1) RoPE table
    rope_table_kernel<<<(L_ * 32) / 256, 256>>>();

    // 2) operand conversions
    convert_f16_kernel<<<(int)(ML * D_ / 4 / 256), 256>>>(x, a);
    transpose_f16_kernel<<<dim3(D_ / 32, 3 * D_ / 32), dim3(32, 8)>>>(
        Wqkv, wq, D_, 3 * D_);
    transpose_f16_kernel<<<dim3(D_ / 32, D_ / 32), dim3(32, 8)>>>(
        Wproj, wp, D_, D_);

    // 3) QKV GEMM with fused RoPE + fp16-split epilogue
    gemm_f16_kernel<1><<<dim3(3 * D_ / 128, (int)(ML / 128)), 256, GEMM_SMEM>>>(
        a, wq, bqkv, nullptr, 3 * D_, D_, qh, ql, kh, vh);

    // 4) tensor-core causal flash attention -> fp16 proj A operand
    attn_mma_kernel<<<dim3(B_ * H_, L_ / 128), 256, AT_SMEM>>>(
        qh, ql, kh, vh, mask, a);

    // 5) output projection
    gemm_f16_kernel<0><<<dim3(D_ / 128, (int)(ML / 128)), 256, GEMM_SMEM>>>(
        a, wp, bproj, out, D_, D_,
        nullptr, nullptr, nullptr, nullptr);
}

// round 16
// speedup vs baseline: 6.5734x; 1.0727x over previous
#include <cuda_runtime.h>
#include <cuda_bf16.h>
#include <cuda_fp16.h>
#include <math.h>
#include <stdint.h>

#define B_  4
#define L_  2048
#define D_  1024
#define H_  16
#define DH  64
#define ML  ((size_t)B_ * L_)          // 8192 rows

// ---------------- scratch (no allocation allowed) ----------------
__device__ float g_cos[L_ * 32];
__device__ float g_sin[L_ * 32];
// fp16 operand buffers
__device__ __half g_a[ML * D_];        // A (x, then att out) single fp16
__device__ __half g_wq[3 * D_ * D_];   // W_qkv^T fp16  [3D, D]
__device__ __half g_wp[D_ * D_];       // W_proj^T fp16 [D, D]
// fp16 attention operands (all [bh][l][64] K-major)
__device__ __half g_qh[ML * D_];       // Q single (x0.125)
__device__ __half g_kh[ML * D_];       // K single
__device__ __half g_vh[ML * D_];       // V single

// ================= helpers =================
__device__ __forceinline__ uint32_t smem_u32(const void* p) {
    uint32_t a;
    asm("{ .reg .u64 t; cvta.to.shared.u64 t, %1; cvt.u32.u64 %0, t; }" : "=r"(a) : "l"(p));
    return a;
}
__device__ __forceinline__ void cp_async16(uint32_t smaddr, const void* gaddr) {
    asm volatile("cp.async.cg.shared.global [%0], [%1], 16;" :: "r"(smaddr), "l"(gaddr));
}
#define CP_COMMIT() asm volatile("cp.async.commit_group;" ::: "memory")
#define CP_WAIT(n)  asm volatile("cp.async.wait_group %0;" :: "n"(n) : "memory")

__device__ __forceinline__ void ldmx4(uint32_t* r, uint32_t addr) {
    asm volatile("ldmatrix.sync.aligned.m8n8.x4.shared.b16 {%0,%1,%2,%3}, [%4];"
        : "=r"(r[0]), "=r"(r[1]), "=r"(r[2]), "=r"(r[3]) : "r"(addr));
}
__device__ __forceinline__ void ldmx4t(uint32_t* r, uint32_t addr) {
    asm volatile("ldmatrix.sync.aligned.m8n8.x4.trans.shared.b16 {%0,%1,%2,%3}, [%4];"
        : "=r"(r[0]), "=r"(r[1]), "=r"(r[2]), "=r"(r[3]) : "r"(addr));
}
__device__ __forceinline__ void mma_f16(float* d, const uint32_t* a, const uint32_t* b) {
    asm volatile("mma.sync.aligned.m16n8k16.row.col.f32.f16.f16.f32 "
        "{%0,%1,%2,%3}, {%4,%5,%6,%7}, {%8,%9}, {%0,%1,%2,%3};"
        : "+f"(d[0]), "+f"(d[1]), "+f"(d[2]), "+f"(d[3])
        : "r"(a[0]), "r"(a[1]), "r"(a[2]), "r"(a[3]), "r"(b[0]), "r"(b[1]));
}
__device__ __forceinline__ uint32_t packh2(float a, float b) {
    __half2 h = __floats2half2_rn(a, b);
    return *reinterpret_cast<uint32_t*>(&h);
}

// ---------------- RoPE table (double-accurate, matches numpy f32 path) ---
__global__ void rope_table_kernel() {
    int idx = blockIdx.x * blockDim.x + threadIdx.x;   // L_*32 = 65536
    int i = idx & 31;
    int l = idx >> 5;
    double invd = exp(-(double)i * (9.210340371976184 / 32.0));
    float invf = (float)invd;
    float freq = (float)l * invf;
    g_cos[idx] = (float)cos((double)freq);
    g_sin[idx] = (float)sin((double)freq);
}

// ---------------- fp32 -> fp16 (elementwise) ----------------------------
__global__ void convert_f16_kernel(const float* __restrict__ in,
    __half* __restrict__ out)
{
    int i = blockIdx.x * blockDim.x + threadIdx.x;    // n/4 threads
    float4 v = ((const float4*)in)[i];
    __half2 p0; p0.x = __float2half(v.x); p0.y = __float2half(v.y);
    __half2 p1; p1.x = __float2half(v.z); p1.y = __float2half(v.w);
    ((__half2*)out)[2 * i] = p0;
    ((__half2*)out)[2 * i + 1] = p1;
}

// ---------------- W [K,N] fp32 -> W^T [N,K] fp16 single -----------------
__global__ void transpose_f16_kernel(const float* __restrict__ W,
    __half* __restrict__ T, int Kd, int Nd)
{
    __shared__ float t[32][33];
    int k0 = blockIdx.x * 32, n0 = blockIdx.y * 32;
    int tx = threadIdx.x, ty = threadIdx.y;
    #pragma unroll
    for (int r = ty; r < 32; r += 8)
        t[r][tx] = W[(size_t)(k0 + r) * Nd + n0 + tx];
    __syncthreads();
    #pragma unroll
    for (int r = ty; r < 32; r += 8)
        T[(size_t)(n0 + r) * Kd + k0 + tx] = __float2half(t[tx][r]);
}

// ---------------- mma.sync fp16 GEMM: A x B^T, 4-stage, occ 2 -----------
// MODE 0: C = A*B^T + bias (fp32 out).  MODE 1: fused QKV epilogue:
// rope+scale, writes Qh/Kh/Vh fp16 directly.
#define T_STRIDE 80
#define T_BYTES  (128 * T_STRIDE)      // 10240
#define BUF2 (2 * T_BYTES)             // A, B = 20480
#define GEMM_SMEM (4 * BUF2)           // 81920

template<int MODE>
__global__ __launch_bounds__(256, 2) void gemm_f16_kernel(
    const __half* __restrict__ Am, const __half* __restrict__ Bm,
    const float* __restrict__ bias, float* __restrict__ C, int N, int K,
    __half* __restrict__ Qh, __half* __restrict__ Kh, __half* __restrict__ Vh)
{
    extern __shared__ char smraw[];
    const uint32_t smb = smem_u32(smraw);
    const int tid = threadIdx.x;
    const int wid = tid >> 5, lane = tid & 31;
    const int wr = wid & 1, wc = wid >> 1;
    const int bn = blockIdx.x * 128, bm = blockIdx.y * 128;

    const char* gp[2];
    gp[0] = (const char*)(Am + (size_t)bm * K);
    gp[1] = (const char*)(Bm + (size_t)bn * K);

    const int NKB = K / 32;            // 32

    auto issue_loads = [&](int kb, int buf) {
        uint32_t sbase = smb + buf * BUF2;
        #pragma unroll
        for (int op = 0; op < 2; op++) {
            #pragma unroll
            for (int half = 0; half < 2; half++) {
                int idx = half * 256 + tid;          // 0..511
                int row = idx >> 2, c = idx & 3;
                const void* g = gp[op] + ((size_t)row * K + kb * 32 + c * 8) * 2;
                uint32_t s = sbase + op * T_BYTES + row * T_STRIDE + c * 16;
                cp_async16(s, g);
            }
        }
    };

    float acc[4][4][4];
    #pragma unroll
    for (int i = 0; i < 4; i++)
        #pragma unroll
        for (int j = 0; j < 4; j++)
            #pragma unroll
            for (int r = 0; r < 4; r++) acc[i][j][r] = 0.f;

    issue_loads(0, 0); CP_COMMIT();
    issue_loads(1, 1); CP_COMMIT();
    issue_loads(2, 2); CP_COMMIT();

    const int lr = lane & 15, lh = lane >> 4;
    const int bj = lane >> 4, bch = (lane >> 3) & 1, bn8 = lane & 7;

    for (int kb = 0; kb < NKB; kb++) {
        if (kb + 2 < NKB)      { CP_WAIT(2); }
        else if (kb + 1 < NKB) { CP_WAIT(1); }
        else                   { CP_WAIT(0); }
        __syncthreads();
        if (kb + 3 < NKB) { issue_loads(kb + 3, (kb + 3) & 3); CP_COMMIT(); }

        uint32_t sA = smb + (kb & 3) * BUF2;
        uint32_t sB = sA + T_BYTES;

        #pragma unroll
        for (int s = 0; s < 2; s++) {
            uint32_t afr[4][4], bfr[4][2];
            #pragma unroll
            for (int i = 0; i < 4; i++) {
                uint32_t off = (uint32_t)((wr * 64 + i * 16 + lr) * T_STRIDE + (s * 2 + lh) * 16);
                ldmx4(afr[i], sA + off);
            }
            #pragma unroll
            for (int jp = 0; jp < 2; jp++) {
                uint32_t tmp[4];
                uint32_t off = (uint32_t)((wc * 32 + (2 * jp + bj) * 8 + bn8) * T_STRIDE
                                          + (s * 2 + bch) * 16);
                ldmx4(tmp, sB + off);
                bfr[2 * jp][0] = tmp[0]; bfr[2 * jp][1] = tmp[1];
                bfr[2 * jp + 1][0] = tmp[2]; bfr[2 * jp + 1][1] = tmp[3];
            }
            #pragma unroll
            for (int i = 0; i < 4; i++)
                #pragma unroll
                for (int j = 0; j < 4; j++)
                    mma_f16(acc[i][j], afr[i], bfr[j]);
        }
    }

    if (MODE == 0) {
        #pragma unroll
        for (int i = 0; i < 4; i++) {
            int row = bm + wr * 64 + i * 16 + (lane >> 2);
            #pragma unroll
            for (int j = 0; j < 4; j++) {
                int col = bn + wc * 32 + j * 8 + 2 * (lane & 3);
                float b0 = bias[col], b1 = bias[col + 1];
                float2 o0; o0.x = acc[i][j][0] + b0; o0.y = acc[i][j][1] + b1;
                float2 o1; o1.x = acc[i][j][2] + b0; o1.y = acc[i][j][3] + b1;
                *(float2*)(C + (size_t)row * N + col) = o0;
                *(float2*)(C + (size_t)(row + 8) * N + col) = o1;
            }
        }
    } else {
        // fused QKV epilogue: col pairs (even, even+1) == rotary pairs
        const int sec = bn >> 10;              // 0=q, 1=k, 2=v (uniform per CTA)
        #pragma unroll
        for (int i = 0; i < 4; i++) {
            #pragma unroll
            for (int rr = 0; rr < 2; rr++) {
                int row = bm + wr * 64 + i * 16 + (lane >> 2) + rr * 8;
                int b = row >> 11, l = row & 2047;
                #pragma unroll
                for (int j = 0; j < 4; j++) {
                    int col = bn + wc * 32 + j * 8 + 2 * (lane & 3);
                    float v0 = acc[i][j][rr * 2 + 0] + bias[col];
                    float v1 = acc[i][j][rr * 2 + 1] + bias[col + 1];
                    int cs = col & 1023;
                    int h = cs >> 6, d = cs & 63, p = d >> 1;
                    size_t off = ((size_t)((b * H_ + h) * L_ + l)) * DH + d;
                    if (sec == 2) {
                        __half2 hh; hh.x = __float2half(v0); hh.y = __float2half(v1);
                        *(__half2*)(Vh + off) = hh;
                    } else {
                        float c = g_cos[l * 32 + p], s = g_sin[l * 32 + p];
                        float y0 = v0 * c - v1 * s;
                        float y1 = v0 * s + v1 * c;
                        if (sec == 0) {
                            y0 *= 0.125f; y1 *= 0.125f;
                            __half2 hh; hh.x = __float2half(y0); hh.y = __float2half(y1);
                            *(__half2*)(Qh + off) = hh;
                        } else {
                            __half2 kk; kk.x = __float2half(y0); kk.y = __float2half(y1);
                            *(__half2*)(Kh + off) = kk;
                        }
                    }
                }
            }
        }
    }
}

// ---------------- tensor-core causal flash attention, 3-stage -----------
// block: 128 q-rows (8 warps x m16), kv tiles of 64. fp16 mma, fp32 softmax.
// Q single fp16 (pre-scaled); K/V single fp16. V fragments via ldmatrix.trans.
#define AT_STRIDE 144
#define AT_KT  (64 * AT_STRIDE)       // 9216
#define AT_BUF (2 * AT_KT)            // K, V = 18432
#define AT_SMEM (3 * AT_BUF + 768)    // 56064 (>= 18432 Q staging)

__global__ __launch_bounds__(256, 1) void attn_mma_kernel(
    const __half* __restrict__ Qh,
    const __half* __restrict__ Kh, const __half* __restrict__ Vh,
    const int* __restrict__ mask,
    __half* __restrict__ Oout)
{
    extern __shared__ char sm[];
    const uint32_t smb = smem_u32(sm);
    const int tid = threadIdx.x, lane = tid & 31, w = tid >> 5;
    const int qt = 15 - (int)blockIdx.y;        // heavy blocks first
    const int bh = blockIdx.x;
    const int b = bh >> 4, h = bh & 15;
    const int qrow0 = qt * 128 + w * 16;

    // ---- stage Q tile into smem, move to register fragments ----
    {
        const __half* s0 = Qh + ((size_t)bh * L_ + qt * 128) * DH;
        #pragma unroll
        for (int c2 = 0; c2 < 4; c2++) {
            int idx = c2 * 256 + tid;            // 0..1023
            int row = idx >> 3, c = idx & 7;
            cp_async16(smb + row * AT_STRIDE + c * 16, s0 + (size_t)row * DH + c * 8);
        }
        CP_COMMIT(); CP_WAIT(0);
        __syncthreads();
    }
    uint32_t qf[4][4];
    {
        const int lr = lane & 15, lhh = lane >> 4;
        #pragma unroll
        for (int kt = 0; kt < 4; kt++) {
            uint32_t off = (uint32_t)((w * 16 + lr) * AT_STRIDE + (kt * 2 + lhh) * 16);
            ldmx4(qf[kt], smb + off);
        }
    }
    __syncthreads();

    const __half* kg  = Kh + (size_t)bh * L_ * DH;
    const __half* vhg = Vh + (size_t)bh * L_ * DH;
    const int* mp = mask + b * L_;

    auto issue = [&](int t, int buf) {
        uint32_t base = smb + buf * AT_BUF;
        int k0 = t * 64;
        #pragma unroll
        for (int hf = 0; hf < 2; hf++) {
            int idx = hf * 256 + tid;            // 0..511
            int row = idx >> 3, c = idx & 7;
            cp_async16(base + row * AT_STRIDE + c * 16,
                       kg + ((size_t)(k0 + row)) * DH + c * 8);
            cp_async16(base + AT_KT + row * AT_STRIDE + c * 16,
                       vhg + ((size_t)(k0 + row)) * DH + c * 8);
        }
        if (tid < 64)
            *(float*)(sm + 3 * AT_BUF + buf * 256 + tid * 4) =
                mp[k0 + tid] ? 0.f : -1e30f;
    };

    float oa[8][4];
    #pragma unroll
    for (int j = 0; j < 8; j++)
        #pragma unroll
        for (int r = 0; r < 4; r++) oa[j][r] = 0.f;
    float m0 = -1e30f, m1 = -1e30f, l0 = 0.f, l1 = 0.f;

    const int nt = (qt + 1) * 2;
    const int bjj = lane >> 4, bch = (lane >> 3) & 1, bn8 = lane & 7;
    const int t4 = (lane & 3) * 2;
    const int rg = lane >> 2;

    issue(0, 0); CP_COMMIT();
    if (nt > 1) { issue(1, 1); CP_COMMIT(); }

    for (int t = 0; t < nt; t++) {
        if (t + 1 < nt) { CP_WAIT(1); } else { CP_WAIT(0); }
        __syncthreads();
        if (t + 2 < nt) { issue(t + 2, (t + 2) % 3); CP_COMMIT(); }

        uint32_t kbase = smb + (t % 3) * AT_BUF;
        const float* kbias = (const float*)(sm + 3 * AT_BUF + (t % 3) * 256);
        int k0 = t * 64;

        // ---- S = Q K^T ----
        float sa[8][4];
        #pragma unroll
        for (int j = 0; j < 8; j++)
            #pragma unroll
            for (int r = 0; r < 4; r++) sa[j][r] = 0.f;
        #pragma unroll
        for (int jp = 0; jp < 4; jp++) {
            #pragma unroll
            for (int kt = 0; kt < 4; kt++) {
                uint32_t tmp[4];
                ldmx4(tmp, kbase + (uint32_t)(((2 * jp + bjj) * 8 + bn8) * AT_STRIDE
                                              + (kt * 2 + bch) * 16));
                mma_f16(sa[2 * jp],     qf[kt], tmp);
                mma_f16(sa[2 * jp + 1], qf[kt], tmp + 2);
            }
        }

        // ---- key bias + causal mask ----
        #pragma unroll
        for (int j = 0; j < 8; j++) {
            float2 kb = *(const float2*)&kbias[j * 8 + t4];
            sa[j][0] += kb.x; sa[j][1] += kb.y;
            sa[j][2] += kb.x; sa[j][3] += kb.y;
        }
        if (k0 + 63 > qrow0) {
            int r0 = qrow0 + rg;
            #pragma unroll
            for (int j = 0; j < 8; j++) {
                int cc = k0 + j * 8 + t4;
                if (cc     > r0)     sa[j][0] = -1e30f;
                if (cc + 1 > r0)     sa[j][1] = -1e30f;
                if (cc     > r0 + 8) sa[j][2] = -1e30f;
                if (cc + 1 > r0 + 8) sa[j][3] = -1e30f;
            }
        }

        // ---- online softmax ----
        float mx0 = -1e30f, mx1 = -1e30f;
        #pragma unroll
        for (int j = 0; j < 8; j++) {
            mx0 = fmaxf(mx0, fmaxf(sa[j][0], sa[j][1]));
            mx1 = fmaxf(mx1, fmaxf(sa[j][2], sa[j][3]));
        }
        mx0 = fmaxf(mx0, __shfl_xor_sync(0xffffffffu, mx0, 1));
        mx0 = fmaxf(mx0, __shfl_xor_sync(0xffffffffu, mx0, 2));
        mx1 = fmaxf(mx1, __shfl_xor_sync(0xffffffffu, mx1, 1));
        mx1 = fmaxf(mx1, __shfl_xor_sync(0xffffffffu, mx1, 2));
        float mn0 = fmaxf(m0, mx0), mn1 = fmaxf(m1, mx1);
        float a0 = __expf(m0 - mn0), a1 = __expf(m1 - mn1);
        m0 = mn0; m1 = mn1;
        float s0 = 0.f, s1 = 0.f;
        #pragma unroll
        for (int j = 0; j < 8; j++) {
            sa[j][0] = __expf(sa[j][0] - mn0);
            sa[j][1] = __expf(sa[j][1] - mn0);
            sa[j][2] = __expf(sa[j][2] - mn1);
            sa[j][3] = __expf(sa[j][3] - mn1);
            s0 += sa[j][0] + sa[j][1];
            s1 += sa[j][2] + sa[j][3];
        }
        s0 += __shfl_xor_sync(0xffffffffu, s0, 1);
        s0 += __shfl_xor_sync(0xffffffffu, s0, 2);
        s1 += __shfl_xor_sync(0xffffffffu, s1, 1);
        s1 += __shfl_xor_sync(0xffffffffu, s1, 2);
        l0 = l0 * a0 + s0;
        l1 = l1 * a1 + s1;

        // ---- P fragments (fp16) ----
        uint32_t pf[4][4];
        #pragma unroll
        for (int kt = 0; kt < 4; kt++) {
            pf[kt][0] = packh2(sa[2 * kt][0],     sa[2 * kt][1]);
            pf[kt][1] = packh2(sa[2 * kt][2],     sa[2 * kt][3]);
            pf[kt][2] = packh2(sa[2 * kt + 1][0], sa[2 * kt + 1][1]);
            pf[kt][3] = packh2(sa[2 * kt + 1][2], sa[2 * kt + 1][3]);
        }

        // ---- O = O*alpha + P V  (V via ldmatrix.trans on [kv][dh] tile) --
        #pragma unroll
        for (int j = 0; j < 8; j++) {
            oa[j][0] *= a0; oa[j][1] *= a0;
            oa[j][2] *= a1; oa[j][3] *= a1;
        }
        uint32_t vhb = kbase + AT_KT;
        #pragma unroll
        for (int jp = 0; jp < 4; jp++) {
            #pragma unroll
            for (int kt = 0; kt < 4; kt++) {
                uint32_t off = (uint32_t)((kt * 16 + bch * 8 + bn8) * AT_STRIDE
                                          + (2 * jp + bjj) * 16);
                uint32_t tv[4];
                ldmx4t(tv, vhb + off);
                mma_f16(oa[2 * jp],     pf[kt], tv);
                mma_f16(oa[2 * jp + 1], pf[kt], tv + 2);
            }
        }
    }

    // ---- epilogue: fp16 straight into proj-GEMM A buffer ----
    float i0 = 1.f / l0, i1 = 1.f / l1;
    int r0 = qrow0 + rg;
    #pragma unroll
    for (int j = 0; j < 8; j++) {
        int col = h * DH + j * 8 + t4;
        float x0 = oa[j][0] * i0, x1 = oa[j][1] * i0;
        float y0 = oa[j][2] * i1, y1 = oa[j][3] * i1;
        __half2 xh; xh.x = __float2half(x0); xh.y = __float2half(x1);
        __half2 yh; yh.x = __float2half(y0); yh.y = __float2half(y1);
        size_t ro0 = ((size_t)(b * L_ + r0)) * D_ + col;
        size_t ro1 = ((size_t)(b * L_ + r0 + 8)) * D_ + col;
        *(__half2*)(Oout + ro0) = xh;
        *(__half2*)(Oout + ro1) = yh;
    }
}

// ---------------- launch ------------------------------------------------
extern "C" void kernel_launch(void* const* d_in, const int* in_sizes, int n_in,
                              void* d_out, int out_size) {
    const float* x     = (const float*)d_in[0];
    const float* Wqkv  = (const float*)d_in[1];
    const float* bqkv  = (const float*)d_in[2];
    const float* Wproj = (const float*)d_in[3];
    const float* bproj = (const float*)d_in[4];
    const int*   mask  = (const int*)d_in[5];
    float* out = (float*)d_out;

    __half *a, *wq, *wp, *qh, *kh, *vh;
    cudaGetSymbolAddress((void**)&a,  g_a);
    cudaGetSymbolAddress((void**)&wq, g_wq);
    cudaGetSymbolAddress((void**)&wp, g_wp);
    cudaGetSymbolAddress((void**)&qh, g_qh);
    cudaGetSymbolAddress((void**)&kh, g_kh);
    cudaGetSymbolAddress((void**)&vh, g_vh);

    cudaFuncSetAttribute(gemm_f16_kernel<0>,
                         cudaFuncAttributeMaxDynamicSharedMemorySize, GEMM_SMEM);
    cudaFuncSetAttribute(gemm_f16_kernel<1>,
                         cudaFuncAttributeMaxDynamicSharedMemorySize, GEMM_SMEM);
    cudaFuncSetAttribute(attn_mma_kernel,
                         cudaFuncAttributeMaxDynamicSharedMemorySize, AT_SMEM);

    // 1) RoPE table
    rope_table_kernel<<<(L_ * 32) / 256, 256>>>();

    // 2) operand conversions
    convert_f16_kernel<<<(int)(ML * D_ / 4 / 256), 256>>>(x, a);
    transpose_f16_kernel<<<dim3(D_ / 32, 3 * D_ / 32), dim3(32, 8)>>>(
        Wqkv, wq, D_, 3 * D_);
    transpose_f16_kernel<<<dim3(D_ / 32, D_ / 32), dim3(32, 8)>>>(
        Wproj, wp, D_, D_);

    // 3) QKV GEMM with fused RoPE + fp16 epilogue
    gemm_f16_kernel<1><<<dim3(3 * D_ / 128, (int)(ML / 128)), 256, GEMM_SMEM>>>(
        a, wq, bqkv, nullptr, 3 * D_, D_, qh, kh, vh);

    // 4) tensor-core causal flash attention -> fp16 proj A operand
    attn_mma_kernel<<<dim3(B_ * H_, L_ / 128), 256, AT_SMEM>>>(
        qh, kh, vh, mask, a);

    // 5) output projection
    gemm_f16_kernel<0><<<dim3(D_ / 128, (int)(ML / 128)), 256, GEMM_SMEM>>>(
        a, wp, bproj, out, D_, D_,
        nullptr, nullptr, nullptr);
}